// round 11
// baseline (speedup 1.0000x reference)
#include <cuda_runtime.h>
#include <math.h>

// ---------------- packed f32x2 helpers (sm_103a FFMA2 path) ----------------
typedef unsigned long long u64t;
__device__ __forceinline__ u64t pack2f(float lo, float hi) {
    u64t r;
    asm("mov.b64 %0, {%1, %2};" : "=l"(r)
        : "r"(__float_as_uint(lo)), "r"(__float_as_uint(hi)));
    return r;
}
__device__ __forceinline__ void ffma2(u64t& d, u64t a, u64t b) {
    asm("fma.rn.f32x2 %0, %1, %2, %0;" : "+l"(d) : "l"(a), "l"(b));
}
__device__ __forceinline__ void unpack2f(u64t v, float& lo, float& hi) {
    unsigned ulo, uhi;
    asm("mov.b64 {%0, %1}, %2;" : "=r"(ulo), "=r"(uhi) : "l"(v));
    lo = __uint_as_float(ulo);
    hi = __uint_as_float(uhi);
}

// ---------------- persistent device scratch (no allocations allowed) ----------------
__device__ float  g_buf0[16u*16u*64u*64u*64u];
__device__ float  g_buf1[16u*32u*32u*32u*32u];
__device__ float  g_buf2[16u*64u*16u*16u*16u];
__device__ float  g_buf3[16u*64u*8u*8u*8u];
__device__ float  g_buf4[16u*64u*4u*4u*4u];
__device__ double g_stats[480];
__device__ float  g_theta[16*12];
__device__ float  g_wT0[32*16*27];
__device__ float  g_wT1[64*32*27];
__device__ float  g_wT2[64*64*27];

// ---------------- prep: zero stats + all three weight transposes ----------------
__global__ void prep_kernel(const float* __restrict__ w0, const float* __restrict__ w1,
                            const float* __restrict__ w2,
                            float* __restrict__ wT0, float* __restrict__ wT1,
                            float* __restrict__ wT2, double* __restrict__ stats) {
    int i = blockIdx.x * 256 + threadIdx.x;
    if (blockIdx.x == 0) {
        // FIX: block has 256 threads; stride to cover all 480 entries.
        for (int k = threadIdx.x; k < 480; k += 256) stats[k] = 0.0;
    }
    if (i < 13824) {                       // w0: cout=32, cin27=432
        int oc = i & 31, icr = i >> 5;
        wT0[i] = w0[oc * 432 + icr];
    } else if (i < 69120) {                // w1: cout=64, cin27=864
        int j = i - 13824;
        int oc = j & 63, icr = j >> 6;
        wT1[j] = w1[oc * 864 + icr];
    } else if (i < 179712) {               // w2: cout=64, cin27=1728
        int j = i - 69120;
        int oc = j & 63, icr = j >> 6;
        wT2[j] = w2[oc * 1728 + icr];
    }
}

// ---------------- BN finalize (inline device helper) ----------------
__device__ __forceinline__ void bn_finalize_smem(
    const double* __restrict__ stats_prev, const float* __restrict__ g_prev,
    const float* __restrict__ be_prev, float invN, int C, int tid,
    float* sScale, float* sShift) {
    if (tid < C) {
        double mean = stats_prev[tid] * (double)invN;
        double var  = stats_prev[C + tid] * (double)invN - mean * mean;
        float a = g_prev[tid] * (float)(1.0 / sqrt(var + 1e-5));
        sScale[tid] = a;
        sShift[tid] = be_prev[tid] - (float)mean * a;
    }
}

// ---------------- conv00 v2: 1->16 ch, stride 1, pad 1, 64^3, FFMA2 ----------------
__global__ void __launch_bounds__(128) conv00_v2(
    const float* __restrict__ x, const float* __restrict__ w,
    const float* __restrict__ bias, float* __restrict__ out,
    double* __restrict__ stats) {
    __shared__ float sIn[1000];
    __shared__ float sWd[864];

    int tid = threadIdx.x;
    int b = blockIdx.y;
    int t = blockIdx.x;
    int tz = t >> 6, ty = (t >> 3) & 7, tx = t & 7;

    for (int i = tid; i < 1000; i += 128) {
        int iz = i / 100, iy = (i / 10) % 10, ix = i % 10;
        int gz = tz * 8 - 1 + iz, gy = ty * 8 - 1 + iy, gx = tx * 8 - 1 + ix;
        float v = 0.f;
        if ((unsigned)gz < 64u && (unsigned)gy < 64u && (unsigned)gx < 64u)
            v = x[((b * 64 + gz) * 64 + gy) * 64 + gx];
        sIn[i] = v;
    }
    for (int i = tid; i < 432; i += 128) {
        int k = i >> 4, oc = i & 15;
        float wv = w[oc * 27 + k];
        sWd[k * 32 + oc * 2]     = wv;
        sWd[k * 32 + oc * 2 + 1] = wv;
    }
    __syncthreads();

    int sz = tid >> 4, sy = (tid >> 1) & 7, sx = tid & 1;

    u64t acc[16][2];
#pragma unroll
    for (int oc = 0; oc < 16; oc++) { acc[oc][0] = 0ULL; acc[oc][1] = 0ULL; }

#pragma unroll
    for (int kd = 0; kd < 3; kd++)
#pragma unroll
        for (int kh = 0; kh < 3; kh++) {
            int base = (sz + kd) * 100 + (sy + kh) * 10 + sx * 4;
            float i0 = sIn[base], i1 = sIn[base + 1], i2 = sIn[base + 2];
            float i3 = sIn[base + 3], i4 = sIn[base + 4], i5 = sIn[base + 5];
            u64t P[5];
            P[0] = pack2f(i0, i1); P[1] = pack2f(i1, i2); P[2] = pack2f(i2, i3);
            P[3] = pack2f(i3, i4); P[4] = pack2f(i4, i5);
            int k9 = kd * 3 + kh;
#pragma unroll
            for (int kw = 0; kw < 3; kw++) {
                const u64t* wrow =
                    reinterpret_cast<const u64t*>(&sWd[(k9 * 3 + kw) * 32]);
#pragma unroll
                for (int oc = 0; oc < 16; oc++) {
                    u64t wp = wrow[oc];
                    ffma2(acc[oc][0], P[kw], wp);
                    ffma2(acc[oc][1], P[kw + 2], wp);
                }
            }
        }

    int gz = tz * 8 + sz, gy = ty * 8 + sy, gx = tx * 8 + sx * 4;
#pragma unroll 1
    for (int oc = 0; oc < 16; oc++) {
        float a0, a1, a2, a3;
        unpack2f(acc[oc][0], a0, a1);
        unpack2f(acc[oc][1], a2, a3);
        float bb = bias[oc];
        a0 += bb; a1 += bb; a2 += bb; a3 += bb;
        *reinterpret_cast<float4*>(&out[(((b * 16 + oc) * 64 + gz) * 64 + gy) * 64 + gx]) =
            make_float4(a0, a1, a2, a3);

        float s = a0 + a1 + a2 + a3;
        float q = a0 * a0 + a1 * a1 + a2 * a2 + a3 * a3;
#pragma unroll
        for (int off = 16; off > 0; off >>= 1) {
            s += __shfl_down_sync(0xffffffffu, s, off);
            q += __shfl_down_sync(0xffffffffu, q, off);
        }
        if ((tid & 31) == 0) {
            atomicAdd(&stats[oc], (double)s);
            atomicAdd(&stats[16 + oc], (double)q);
        }
    }
}

// ---------------- conv_s2_v8: slot-offset loader + inlined BN finalize -------------
template <int CIN, int COUTT, int COUTB, int OCPT, int ICC, int MAXB>
__global__ void __launch_bounds__(128, MAXB) conv_s2_v8(
    const float* __restrict__ in, const float* __restrict__ wT,
    const float* __restrict__ bias,
    const double* __restrict__ statsPrev, const float* __restrict__ gPrev,
    const float* __restrict__ bePrev, float invN,
    float* __restrict__ out, double* __restrict__ stats,
    int Din, int Dout, int ntx, int nty) {
    constexpr int GROUPS = COUTB / OCPT;
    constexpr int THREADS = 32 * GROUPS;
    constexpr int NPAIR = OCPT / 2;
    constexpr int IZ = 9, IYE = 9, IX = 17, IXP2 = 18;
    constexpr int NINU = ICC * IZ * IYE * IXP2;
    constexpr int NSLOT = (NINU + THREADS - 1) / THREADS;
    constexpr int NW = COUTB * ICC * 27;
    static_assert(THREADS == 128, "tile mapping assumes 128 threads");
    static_assert((NPAIR & 1) == 0, "NPAIR must be even");

    extern __shared__ float sm[];
    u64t*  sInD = reinterpret_cast<u64t*>(sm);
    float* sW   = sm + 2 * NSLOT * THREADS;
    __shared__ float bsum[COUTB], bsq[COUTB];
    __shared__ float sScale[CIN], sShift[CIN];

    int tid = threadIdx.x;
    int b = blockIdx.y;
    int ocBase = blockIdx.z * COUTB;
    int t = blockIdx.x;
    int tx = t % ntx, ty = (t / ntx) % nty, tz = t / (ntx * nty);

    int vt = tid & 31;
    int group = tid >> 5;
    int oxv = vt & 1;
    int oy  = (vt >> 1) & 3;
    int oz  = vt >> 3;

    // inline BN finalize of previous stage
    bn_finalize_smem(statsPrev, gPrev, bePrev, invN, CIN, tid, sScale, sShift);

    int ginz = tz * 8 - 1;
    int giny = ty * 8 - 1;
    int ginx = tx * 16 - 1;

    const float* inB = in + (long long)b * CIN * Din * Din * Din;
    const int chanStride = Din * Din * Din;

    // per-slot packed offsets (once per block)
    int goff[NSLOT];
    {
        int i = tid;
#pragma unroll
        for (int s = 0; s < NSLOT; s++, i += THREADS) {
            int ix = i % IXP2;
            int r  = i / IXP2;
            int iy = r % IYE;
            int r2 = r / IYE;
            int iz = r2 % IZ;
            int icl = r2 / IZ;
            int gz = ginz + iz, gy = giny + iy, gx = ginx + ix;
            bool ok = (i < NINU) && (ix < IX) &&
                      ((unsigned)gz < (unsigned)Din) &&
                      ((unsigned)gy < (unsigned)Din) &&
                      ((unsigned)gx < (unsigned)Din);
            int off = ((icl * Din + gz) * Din + gy) * Din + gx;
            goff[s] = ok ? (off | (icl << 24)) : -1;
        }
    }

    u64t acc[NPAIR][4];
#pragma unroll
    for (int p = 0; p < NPAIR; p++)
#pragma unroll
        for (int u = 0; u < 4; u++) acc[p][u] = 0ULL;

    // prologue prefetch
    float pre[NSLOT];
#pragma unroll
    for (int s = 0; s < NSLOT; s++) {
        int pk = goff[s];
        pre[s] = (pk >= 0) ? __ldg(inB + (pk & 0x00FFFFFF)) : 0.f;
    }

#pragma unroll 1
    for (int c0 = 0; c0 < CIN; c0 += ICC) {
        __syncthreads();   // prev compute done; also covers sScale init at c0=0
#pragma unroll
        for (int s = 0; s < NSLOT; s++) {
            int pk = goff[s];
            float v = 0.f;
            if (pk >= 0) {
                int icl = pk >> 24;
                v = fmaxf(fmaf(pre[s], sScale[c0 + icl], sShift[c0 + icl]), 0.f);
            }
            sInD[s * THREADS + tid] = pack2f(v, v);
        }
        {
            const float* srcw = wT + c0 * 27 * COUTT;
            if (COUTB == COUTT) {
#pragma unroll
                for (int i = tid * 4; i < NW; i += THREADS * 4)
                    *reinterpret_cast<float4*>(&sW[i]) =
                        *reinterpret_cast<const float4*>(&srcw[i]);
            } else {
#pragma unroll
                for (int i = tid * 4; i < NW; i += THREADS * 4) {
                    int ocl = i % COUTB;
                    int row = i / COUTB;
                    *reinterpret_cast<float4*>(&sW[i]) =
                        *reinterpret_cast<const float4*>(&srcw[row * COUTT + ocBase + ocl]);
                }
            }
        }
        __syncthreads();

        if (c0 + ICC < CIN) {
            const float* inC2 = inB + (c0 + ICC) * chanStride;
#pragma unroll
            for (int s = 0; s < NSLOT; s++) {
                int pk = goff[s];
                pre[s] = (pk >= 0) ? __ldg(inC2 + (pk & 0x00FFFFFF)) : 0.f;
            }
        }

#pragma unroll
        for (int ic = 0; ic < ICC; ic++) {
#pragma unroll
            for (int kd = 0; kd < 3; kd++)
#pragma unroll
                for (int kh = 0; kh < 3; kh++) {
                    const u64t* ip =
                        &sInD[((ic * IZ + (2 * oz + kd)) * IYE + (2 * oy + kh)) * IXP2 +
                              8 * oxv];
                    ulonglong2 q0 = *reinterpret_cast<const ulonglong2*>(ip);
                    ulonglong2 q1 = *reinterpret_cast<const ulonglong2*>(ip + 2);
                    ulonglong2 q2 = *reinterpret_cast<const ulonglong2*>(ip + 4);
                    ulonglong2 q3 = *reinterpret_cast<const ulonglong2*>(ip + 6);
                    u64t iv8 = ip[8];
                    u64t ivd[9] = {q0.x, q0.y, q1.x, q1.y, q2.x, q2.y, q3.x, q3.y, iv8};
                    int k9 = kd * 3 + kh;
                    const float* wb_ = &sW[(ic * 27 + k9 * 3) * COUTB + group * OCPT];
#pragma unroll
                    for (int kw = 0; kw < 3; kw++) {
                        ulonglong2 wq[NPAIR / 2];
#pragma unroll
                        for (int pp = 0; pp < NPAIR / 2; pp++)
                            wq[pp] = *reinterpret_cast<const ulonglong2*>(
                                wb_ + kw * COUTB + pp * 4);
#pragma unroll
                        for (int u = 0; u < 4; u++) {
                            u64t iv = ivd[2 * u + kw];
#pragma unroll
                            for (int pp = 0; pp < NPAIR / 2; pp++) {
                                ffma2(acc[2 * pp][u], wq[pp].x, iv);
                                ffma2(acc[2 * pp + 1][u], wq[pp].y, iv);
                            }
                        }
                    }
                }
        }
    }

    int gz = tz * 4 + oz, gy = ty * 4 + oy;
    int gx = tx * 8 + oxv * 4;
#pragma unroll 1
    for (int p = 0; p < NPAIR; p++) {
        float o0[4], o1[4];
#pragma unroll
        for (int u = 0; u < 4; u++) unpack2f(acc[p][u], o0[u], o1[u]);
#pragma unroll
        for (int h = 0; h < 2; h++) {
            float* ov = h ? o1 : o0;
            int ocl = group * OCPT + 2 * p + h;
            int oc = ocBase + ocl;
            float bb = bias[oc];
            float a0 = ov[0] + bb, a1 = ov[1] + bb, a2 = ov[2] + bb, a3 = ov[3] + bb;
            *reinterpret_cast<float4*>(
                &out[(((b * COUTT + oc) * Dout + gz) * Dout + gy) * Dout + gx]) =
                make_float4(a0, a1, a2, a3);

            float s = a0 + a1 + a2 + a3;
            float q = a0 * a0 + a1 * a1 + a2 * a2 + a3 * a3;
#pragma unroll
            for (int off = 16; off > 0; off >>= 1) {
                s += __shfl_down_sync(0xffffffffu, s, off);
                q += __shfl_down_sync(0xffffffffu, q, off);
            }
            if (vt == 0) { bsum[ocl] = s; bsq[ocl] = q; }
        }
    }
    __syncthreads();
    if (tid < COUTB) {
        atomicAdd(&stats[ocBase + tid], (double)bsum[tid]);
        atomicAdd(&stats[COUTT + ocBase + tid], (double)bsq[tid]);
    }
}

// ---------------- old generic stride-2 conv (stage 4) + inline finalize ------------
template <int CIN, int COUTB, int OCPT>
__global__ void __launch_bounds__(128) conv_s2_kernel(
    const float* __restrict__ in, const float* __restrict__ w,
    const float* __restrict__ bias,
    const double* __restrict__ statsPrev, const float* __restrict__ gPrev,
    const float* __restrict__ bePrev, float invN,
    float* __restrict__ out, double* __restrict__ stats,
    int Din, int Dout, int ntile, int coutTot) {
    constexpr int ICC = 16;
    constexpr int NIN = ICC * 729;
    constexpr int NW  = COUTB * ICC * 27;
    extern __shared__ float sm[];
    float* sIn = sm;
    float* sW  = sm + NIN;
    __shared__ float bsum[COUTB], bsq[COUTB];
    __shared__ float sScale[CIN], sShift[CIN];

    int tid = threadIdx.x;
    int b = blockIdx.y;
    int ocBase = blockIdx.z * COUTB;
    int t = blockIdx.x;
    int tz = t / (ntile * ntile), ty = (t / ntile) % ntile, tx = t % ntile;
    int pair = tid & 31, group = tid >> 5;
    int oz = pair >> 3, oy = (pair >> 1) & 3, px = pair & 1;

    bn_finalize_smem(statsPrev, gPrev, bePrev, invN, CIN, tid, sScale, sShift);

    if (tid < COUTB) { bsum[tid] = 0.f; bsq[tid] = 0.f; }

    float acc0[OCPT], acc1[OCPT];
#pragma unroll
    for (int j = 0; j < OCPT; j++) { acc0[j] = 0.f; acc1[j] = 0.f; }

    for (int c0 = 0; c0 < CIN; c0 += ICC) {
        __syncthreads();
        for (int i = tid; i < NIN; i += 128) {
            int ic = i / 729, r = i % 729;
            int iz = r / 81, iy = (r / 9) % 9, ix = r % 9;
            int gz = tz * 8 - 1 + iz, gy = ty * 8 - 1 + iy, gx = tx * 8 - 1 + ix;
            float v = 0.f;
            if ((unsigned)gz < (unsigned)Din && (unsigned)gy < (unsigned)Din &&
                (unsigned)gx < (unsigned)Din) {
                v = in[(((b * CIN + c0 + ic) * Din + gz) * Din + gy) * Din + gx];
                v = fmaxf(fmaf(v, sScale[c0 + ic], sShift[c0 + ic]), 0.f);
            }
            sIn[i] = v;
        }
        for (int i = tid; i < NW; i += 128) {
            int ocl = i / (ICC * 27), r = i % (ICC * 27);
            sW[i] = w[((ocBase + ocl) * CIN + c0) * 27 + r];
        }
        __syncthreads();

#pragma unroll 1
        for (int ic = 0; ic < ICC; ic++) {
            const float* wrow = &sW[(group * OCPT) * ICC * 27 + ic * 27];
#pragma unroll
            for (int kd = 0; kd < 3; kd++)
#pragma unroll
                for (int kh = 0; kh < 3; kh++) {
                    int base = ((ic * 9 + (2 * oz + kd)) * 9 + (2 * oy + kh)) * 9 + 4 * px;
                    float ivs[5];
#pragma unroll
                    for (int u = 0; u < 5; u++) ivs[u] = sIn[base + u];
#pragma unroll
                    for (int kw = 0; kw < 3; kw++) {
#pragma unroll
                        for (int j = 0; j < OCPT; j++) {
                            float wv = wrow[j * ICC * 27 + (kd * 3 + kh) * 3 + kw];
                            acc0[j] = fmaf(ivs[kw], wv, acc0[j]);
                            acc1[j] = fmaf(ivs[kw + 2], wv, acc1[j]);
                        }
                    }
                }
        }
    }

    int gz = tz * 4 + oz, gy = ty * 4 + oy, gx = tx * 4 + 2 * px;
#pragma unroll
    for (int j = 0; j < OCPT; j++) {
        int oc = ocBase + group * OCPT + j;
        float bb = bias[oc];
        float o0 = acc0[j] + bb, o1 = acc1[j] + bb;
        *reinterpret_cast<float2*>(
            &out[(((b * coutTot + oc) * Dout + gz) * Dout + gy) * Dout + gx]) =
            make_float2(o0, o1);

        float s = o0 + o1, q = o0 * o0 + o1 * o1;
#pragma unroll
        for (int off = 16; off > 0; off >>= 1) {
            s += __shfl_down_sync(0xffffffffu, s, off);
            q += __shfl_down_sync(0xffffffffu, q, off);
        }
        if (pair == 0) {
            atomicAdd(&bsum[group * OCPT + j], s);
            atomicAdd(&bsq[group * OCPT + j], q);
        }
    }
    __syncthreads();
    if (tid < COUTB) {
        atomicAdd(&stats[ocBase + tid], (double)bsum[tid]);
        atomicAdd(&stats[coutTot + ocBase + tid], (double)bsq[tid]);
    }
}

// ---------------- heads: BN finalize + 12 dot products + matrix composition --------
__device__ __forceinline__ void ident4(float* M) {
#pragma unroll
    for (int i = 0; i < 16; i++) M[i] = (i % 5 == 0) ? 1.f : 0.f;
}
__device__ __forceinline__ void mm4(const float* A, const float* B, float* C) {
#pragma unroll
    for (int i = 0; i < 4; i++)
#pragma unroll
        for (int j = 0; j < 4; j++)
            C[i * 4 + j] = A[i * 4 + 0] * B[0 + j] + A[i * 4 + 1] * B[4 + j] +
                           A[i * 4 + 2] * B[8 + j] + A[i * 4 + 3] * B[12 + j];
}

__global__ void __launch_bounds__(256) heads_kernel(
    const float* __restrict__ xs,
    const double* __restrict__ statsPrev, const float* __restrict__ gPrev,
    const float* __restrict__ bePrev, float invN,
    const float* __restrict__ tw, const float* __restrict__ tb,
    const float* __restrict__ rw, const float* __restrict__ rb,
    const float* __restrict__ sw_, const float* __restrict__ sb_,
    const float* __restrict__ shw, const float* __restrict__ shb,
    float* __restrict__ theta) {
    __shared__ float red[12 * 256];
    __shared__ float ssc[64], ssh[64];
    int b = blockIdx.x, tid = threadIdx.x;
    bn_finalize_smem(statsPrev, gPrev, bePrev, invN, 64, tid, ssc, ssh);
    __syncthreads();
    float p[12];
#pragma unroll
    for (int r = 0; r < 12; r++) p[r] = 0.f;
    for (int i = tid; i < 4096; i += 256) {
        int c = i >> 6;
        float v = fmaxf(fmaf(xs[b * 4096 + i], ssc[c], ssh[c]), 0.f);
#pragma unroll
        for (int r = 0; r < 3; r++) {
            p[r]     = fmaf(v, tw[r * 4096 + i], p[r]);
            p[3 + r] = fmaf(v, rw[r * 4096 + i], p[3 + r]);
            p[6 + r] = fmaf(v, sw_[r * 4096 + i], p[6 + r]);
            p[9 + r] = fmaf(v, shw[r * 4096 + i], p[9 + r]);
        }
    }
#pragma unroll
    for (int r = 0; r < 12; r++) red[r * 256 + tid] = p[r];
    __syncthreads();
    for (int s = 128; s > 0; s >>= 1) {
        if (tid < s)
#pragma unroll
            for (int r = 0; r < 12; r++) red[r * 256 + tid] += red[r * 256 + tid + s];
        __syncthreads();
    }
    if (tid == 0) {
        const float PI4 = 0.7853981633974483f;
        float tr[3], ro[3], scp[3], shp[3];
#pragma unroll
        for (int r = 0; r < 3; r++) {
            tr[r]  = tanhf(red[r * 256] + tb[r]) * 0.1f;
            ro[r]  = tanhf(red[(3 + r) * 256] + rb[r]) * PI4;
            scp[r] = tanhf(red[(6 + r) * 256] + sb_[r]) * 0.2f;
            shp[r] = tanhf(red[(9 + r) * 256] + shb[r]) * PI4;
        }
        float c0 = cosf(ro[0]), s0 = sinf(ro[0]);
        float c1 = cosf(ro[1]), s1 = sinf(ro[1]);
        float c2 = cosf(ro[2]), s2 = sinf(ro[2]);
        float cs0 = cosf(shp[0]), ss0 = sinf(shp[0]);
        float cs1 = cosf(shp[1]), ss1 = sinf(shp[1]);
        float cs2 = cosf(shp[2]), ss2 = sinf(shp[2]);

        float T[16], R1[16], R2[16], R3[16], S[16], H1[16], H2[16], H3[16];
        float R[16], Sh[16], ShT[16], A[16], B[16];
        ident4(T);  T[3] = tr[0]; T[7] = tr[1]; T[11] = tr[2];
        ident4(R1); R1[0] = c0; R1[1] = -s0; R1[4] = s0; R1[5] = c0;
        ident4(R2); R2[5] = c1; R2[6] = -s1; R2[9] = s1; R2[10] = c1;
        ident4(R3); R3[0] = c2; R3[1] = -s2; R3[4] = s2; R3[5] = c2;
        ident4(S);  S[0] = expf(scp[0]); S[5] = expf(scp[1]); S[10] = expf(scp[2]);
        ident4(H1); H1[5] = cs0; H1[6] = -ss0; H1[9] = ss0; H1[10] = cs0;
        ident4(H2); H2[0] = cs1; H2[2] = ss1; H2[8] = -ss1; H2[10] = cs1;
        ident4(H3); H3[0] = cs2; H3[1] = -ss2; H3[4] = ss2; H3[5] = cs2;

        mm4(R1, R2, A); mm4(A, R3, R);
        mm4(H1, H2, A); mm4(A, H3, Sh);
#pragma unroll
        for (int i = 0; i < 4; i++)
#pragma unroll
            for (int j = 0; j < 4; j++) ShT[i * 4 + j] = Sh[j * 4 + i];
        mm4(Sh, S, A); mm4(A, ShT, B); mm4(B, R, A); mm4(A, T, B);
#pragma unroll
        for (int i = 0; i < 12; i++) theta[b * 12 + i] = B[i];
    }
}

// ---------------- trilinear grid sample (zero padding, clamped gather) ----------------
__global__ void __launch_bounds__(256) sampler_kernel(
    const float* __restrict__ x, const float* __restrict__ theta,
    float* __restrict__ out) {
    int idx = blockIdx.x * 256 + threadIdx.x;
    int b = idx >> 18;
    int r = idx & 262143;
    int z = r >> 12, y = (r >> 6) & 63, xq = r & 63;
    const float st = 2.f / 63.f;
    float xx = fmaf((float)xq, st, -1.f);
    float yy = fmaf((float)y, st, -1.f);
    float zz = fmaf((float)z, st, -1.f);
    const float* th = &theta[b * 12];
    float g0 = th[0] * xx + th[1] * yy + th[2] * zz + th[3];
    float g1 = th[4] * xx + th[5] * yy + th[6] * zz + th[7];
    float g2 = th[8] * xx + th[9] * yy + th[10] * zz + th[11];
    float fx = ((g0 + 1.f) * 64.f - 1.f) * 0.5f;
    float fy = ((g1 + 1.f) * 64.f - 1.f) * 0.5f;
    float fz = ((g2 + 1.f) * 64.f - 1.f) * 0.5f;
    float x0f = floorf(fx), y0f = floorf(fy), z0f = floorf(fz);
    int x0 = (int)x0f, y0 = (int)y0f, z0 = (int)z0f;
    float wx1 = fx - x0f, wx0 = 1.f - wx1;
    float wy1 = fy - y0f, wy0 = 1.f - wy1;
    float wz1 = fz - z0f, wz0 = 1.f - wz1;
    const float* xb = &x[b << 18];
    float acc = 0.f;
#pragma unroll
    for (int dz = 0; dz < 2; dz++) {
        int zc = z0 + dz;
        float wz = dz ? wz1 : wz0;
        bool vz = (zc >= 0 && zc < 64);
        int zi = min(max(zc, 0), 63);
#pragma unroll
        for (int dy = 0; dy < 2; dy++) {
            int yc = y0 + dy;
            float wy = dy ? wy1 : wy0;
            bool vy = vz && (yc >= 0 && yc < 64);
            int yi = min(max(yc, 0), 63);
#pragma unroll
            for (int dx = 0; dx < 2; dx++) {
                int xc = x0 + dx;
                float wgt = wz * wy * (dx ? wx1 : wx0);
                bool v = vy && (xc >= 0 && xc < 64);
                int xi = min(max(xc, 0), 63);
                float val = xb[(zi * 64 + yi) * 64 + xi];
                acc += v ? val * wgt : 0.f;
            }
        }
    }
    out[idx] = acc;
}

// ---------------- launch ----------------
extern "C" void kernel_launch(void* const* d_in, const int* in_sizes, int n_in,
                              void* d_out, int out_size) {
    const float* x    = (const float*)d_in[0];
    const float* w00  = (const float*)d_in[1];
    const float* b00  = (const float*)d_in[2];
    const float* g00  = (const float*)d_in[3];
    const float* be00 = (const float*)d_in[4];
    const float* w0   = (const float*)d_in[5];
    const float* b0   = (const float*)d_in[6];
    const float* g0   = (const float*)d_in[7];
    const float* be0  = (const float*)d_in[8];
    const float* w1   = (const float*)d_in[9];
    const float* b1   = (const float*)d_in[10];
    const float* g1   = (const float*)d_in[11];
    const float* be1  = (const float*)d_in[12];
    const float* w2   = (const float*)d_in[13];
    const float* b2   = (const float*)d_in[14];
    const float* g2   = (const float*)d_in[15];
    const float* be2  = (const float*)d_in[16];
    const float* w3   = (const float*)d_in[17];
    const float* b3   = (const float*)d_in[18];
    const float* g3   = (const float*)d_in[19];
    const float* be3  = (const float*)d_in[20];
    const float* tw   = (const float*)d_in[21];
    const float* tb   = (const float*)d_in[22];
    const float* rw   = (const float*)d_in[23];
    const float* rb   = (const float*)d_in[24];
    const float* sw   = (const float*)d_in[25];
    const float* sb   = (const float*)d_in[26];
    const float* shw  = (const float*)d_in[27];
    const float* shb  = (const float*)d_in[28];

    float *buf0, *buf1, *buf2, *buf3, *buf4, *theta;
    float *wT0, *wT1, *wT2;
    double* stats;
    cudaGetSymbolAddress((void**)&buf0, g_buf0);
    cudaGetSymbolAddress((void**)&buf1, g_buf1);
    cudaGetSymbolAddress((void**)&buf2, g_buf2);
    cudaGetSymbolAddress((void**)&buf3, g_buf3);
    cudaGetSymbolAddress((void**)&buf4, g_buf4);
    cudaGetSymbolAddress((void**)&stats, g_stats);
    cudaGetSymbolAddress((void**)&theta, g_theta);
    cudaGetSymbolAddress((void**)&wT0, g_wT0);
    cudaGetSymbolAddress((void**)&wT1, g_wT1);
    cudaGetSymbolAddress((void**)&wT2, g_wT2);

    // smem sizes (input 23 slots * 128 thr * 8B = 23552)
    const int SM_S1 = 23 * 128 * 8 + 32 * 2 * 27 * 4;  // 30464
    const int SM_S2 = 23 * 128 * 8 + 32 * 2 * 27 * 4;  // 30464 (COUTB=32)
    const int SM_S3 = 23 * 128 * 8 + 16 * 2 * 27 * 4;  // 27008 (COUTB=16)
    const int SM_L4 = (16 * 729 + 16 * 16 * 27) * 4;   // 74304 (stage 4)
    cudaFuncSetAttribute(conv_s2_v8<16, 32, 32, 8, 2, 4>,
                         cudaFuncAttributeMaxDynamicSharedMemorySize, SM_S1);
    cudaFuncSetAttribute(conv_s2_v8<32, 64, 32, 8, 2, 4>,
                         cudaFuncAttributeMaxDynamicSharedMemorySize, SM_S2);
    cudaFuncSetAttribute(conv_s2_v8<64, 64, 16, 4, 2, 4>,
                         cudaFuncAttributeMaxDynamicSharedMemorySize, SM_S3);
    cudaFuncSetAttribute(conv_s2_kernel<64, 16, 4>,
                         cudaFuncAttributeMaxDynamicSharedMemorySize, SM_L4);

    // 1: prep (zero stats + all weight transposes)
    prep_kernel<<<702, 256>>>(w0, w1, w2, wT0, wT1, wT2, stats);

    // 2: conv00 1->16, 64^3
    conv00_v2<<<dim3(512, 16), 128>>>(x, w00, b00, buf0, stats + 0);

    // 3: stage 1: 16->32, 64^3 -> 32^3; 256 tiles
    conv_s2_v8<16, 32, 32, 8, 2, 4><<<dim3(256, 16, 1), 128, SM_S1>>>(
        buf0, wT0, b0, stats + 0, g00, be00, 1.f / 4194304.f,
        buf1, stats + 32, 64, 32, 4, 8);

    // 4: stage 2: 32->64, 32^3 -> 16^3; 32 tiles x oc-split z=2 -> 1024 blocks
    conv_s2_v8<32, 64, 32, 8, 2, 4><<<dim3(32, 16, 2), 128, SM_S2>>>(
        buf1, wT1, b1, stats + 32, g0, be0, 1.f / 524288.f,
        buf2, stats + 96, 32, 16, 2, 4);

    // 5: stage 3: 64->64, 16^3 -> 8^3; 4 tiles x oc-split z=4 -> 256 blocks
    conv_s2_v8<64, 64, 16, 4, 2, 4><<<dim3(4, 16, 4), 128, SM_S3>>>(
        buf2, wT2, b2, stats + 96, g1, be1, 1.f / 65536.f,
        buf3, stats + 224, 16, 8, 1, 2);

    // 6: stage 4: 64->64, 8^3 -> 4^3 (tiny; old kernel, oc split z=4)
    conv_s2_kernel<64, 16, 4><<<dim3(1, 16, 4), 128, SM_L4>>>(
        buf3, w3, b3, stats + 224, g2, be2, 1.f / 8192.f,
        buf4, stats + 352, 8, 4, 1, 64);

    // 7: heads (inlines stage-4 BN finalize)
    heads_kernel<<<16, 256>>>(buf4, stats + 352, g3, be3, 1.f / 1024.f,
                              tw, tb, rw, rb, sw, sb, shw, shb, theta);

    // 8: grid sample
    sampler_kernel<<<16384, 256>>>(x, theta, (float*)d_out);
}

// round 12
// speedup vs baseline: 1.0902x; 1.0902x over previous
#include <cuda_runtime.h>
#include <math.h>

// ---------------- packed f32x2 helpers (sm_103a FFMA2 path) ----------------
typedef unsigned long long u64t;
__device__ __forceinline__ u64t pack2f(float lo, float hi) {
    u64t r;
    asm("mov.b64 %0, {%1, %2};" : "=l"(r)
        : "r"(__float_as_uint(lo)), "r"(__float_as_uint(hi)));
    return r;
}
__device__ __forceinline__ void ffma2(u64t& d, u64t a, u64t b) {
    asm("fma.rn.f32x2 %0, %1, %2, %0;" : "+l"(d) : "l"(a), "l"(b));
}
__device__ __forceinline__ void unpack2f(u64t v, float& lo, float& hi) {
    unsigned ulo, uhi;
    asm("mov.b64 {%0, %1}, %2;" : "=r"(ulo), "=r"(uhi) : "l"(v));
    lo = __uint_as_float(ulo);
    hi = __uint_as_float(uhi);
}

// ---------------- persistent device scratch ----------------
__device__ float  g_buf0[16u*16u*64u*64u*64u];
__device__ float  g_buf1[16u*32u*32u*32u*32u];
__device__ float  g_buf2[16u*64u*16u*16u*16u];
__device__ float  g_buf3[16u*64u*8u*8u*8u];
__device__ float  g_buf4[16u*64u*4u*4u*4u];
__device__ double g_stats[480];
__device__ float  g_theta[16*12];
__device__ float  g_wT0[32*16*27];
__device__ float  g_wT1[64*32*27];
__device__ float  g_wT2[64*64*27];

// ---------------- prep: zero stats + all three weight transposes ----------------
__global__ void prep_kernel(const float* __restrict__ w0, const float* __restrict__ w1,
                            const float* __restrict__ w2,
                            float* __restrict__ wT0, float* __restrict__ wT1,
                            float* __restrict__ wT2, double* __restrict__ stats) {
    int i = blockIdx.x * 256 + threadIdx.x;
    if (blockIdx.x == 0) {
        for (int k = threadIdx.x; k < 480; k += 256) stats[k] = 0.0;
    }
    if (i < 13824) {                       // w0: cout=32, cin27=432
        int oc = i & 31, icr = i >> 5;
        wT0[i] = w0[oc * 432 + icr];
    } else if (i < 69120) {                // w1: cout=64, cin27=864
        int j = i - 13824;
        int oc = j & 63, icr = j >> 6;
        wT1[j] = w1[oc * 864 + icr];
    } else if (i < 179712) {               // w2: cout=64, cin27=1728
        int j = i - 69120;
        int oc = j & 63, icr = j >> 6;
        wT2[j] = w2[oc * 1728 + icr];
    }
}

// ---------------- BN finalize (inline device helper) ----------------
__device__ __forceinline__ void bn_finalize_smem(
    const double* __restrict__ stats_prev, const float* __restrict__ g_prev,
    const float* __restrict__ be_prev, float invN, int C, int tid,
    float* sScale, float* sShift) {
    if (tid < C) {
        double mean = stats_prev[tid] * (double)invN;
        double var  = stats_prev[C + tid] * (double)invN - mean * mean;
        float a = g_prev[tid] * (float)(1.0 / sqrt(var + 1e-5));
        sScale[tid] = a;
        sShift[tid] = be_prev[tid] - (float)mean * a;
    }
}

// ---------------- conv00 v2: 1->16 ch, stride 1, pad 1, 64^3, FFMA2 ----------------
__global__ void __launch_bounds__(128) conv00_v2(
    const float* __restrict__ x, const float* __restrict__ w,
    const float* __restrict__ bias, float* __restrict__ out,
    double* __restrict__ stats) {
    __shared__ float sIn[1000];
    __shared__ float sWd[864];

    int tid = threadIdx.x;
    int b = blockIdx.y;
    int t = blockIdx.x;
    int tz = t >> 6, ty = (t >> 3) & 7, tx = t & 7;

    for (int i = tid; i < 1000; i += 128) {
        int iz = i / 100, iy = (i / 10) % 10, ix = i % 10;
        int gz = tz * 8 - 1 + iz, gy = ty * 8 - 1 + iy, gx = tx * 8 - 1 + ix;
        float v = 0.f;
        if ((unsigned)gz < 64u && (unsigned)gy < 64u && (unsigned)gx < 64u)
            v = x[((b * 64 + gz) * 64 + gy) * 64 + gx];
        sIn[i] = v;
    }
    for (int i = tid; i < 432; i += 128) {
        int k = i >> 4, oc = i & 15;
        float wv = w[oc * 27 + k];
        sWd[k * 32 + oc * 2]     = wv;
        sWd[k * 32 + oc * 2 + 1] = wv;
    }
    __syncthreads();

    int sz = tid >> 4, sy = (tid >> 1) & 7, sx = tid & 1;

    u64t acc[16][2];
#pragma unroll
    for (int oc = 0; oc < 16; oc++) { acc[oc][0] = 0ULL; acc[oc][1] = 0ULL; }

#pragma unroll
    for (int kd = 0; kd < 3; kd++)
#pragma unroll
        for (int kh = 0; kh < 3; kh++) {
            int base = (sz + kd) * 100 + (sy + kh) * 10 + sx * 4;
            float i0 = sIn[base], i1 = sIn[base + 1], i2 = sIn[base + 2];
            float i3 = sIn[base + 3], i4 = sIn[base + 4], i5 = sIn[base + 5];
            u64t P[5];
            P[0] = pack2f(i0, i1); P[1] = pack2f(i1, i2); P[2] = pack2f(i2, i3);
            P[3] = pack2f(i3, i4); P[4] = pack2f(i4, i5);
            int k9 = kd * 3 + kh;
#pragma unroll
            for (int kw = 0; kw < 3; kw++) {
                const u64t* wrow =
                    reinterpret_cast<const u64t*>(&sWd[(k9 * 3 + kw) * 32]);
#pragma unroll
                for (int oc = 0; oc < 16; oc++) {
                    u64t wp = wrow[oc];
                    ffma2(acc[oc][0], P[kw], wp);
                    ffma2(acc[oc][1], P[kw + 2], wp);
                }
            }
        }

    int gz = tz * 8 + sz, gy = ty * 8 + sy, gx = tx * 8 + sx * 4;
#pragma unroll 1
    for (int oc = 0; oc < 16; oc++) {
        float a0, a1, a2, a3;
        unpack2f(acc[oc][0], a0, a1);
        unpack2f(acc[oc][1], a2, a3);
        float bb = bias[oc];
        a0 += bb; a1 += bb; a2 += bb; a3 += bb;
        *reinterpret_cast<float4*>(&out[(((b * 16 + oc) * 64 + gz) * 64 + gy) * 64 + gx]) =
            make_float4(a0, a1, a2, a3);

        float s = a0 + a1 + a2 + a3;
        float q = a0 * a0 + a1 * a1 + a2 * a2 + a3 * a3;
#pragma unroll
        for (int off = 16; off > 0; off >>= 1) {
            s += __shfl_down_sync(0xffffffffu, s, off);
            q += __shfl_down_sync(0xffffffffu, q, off);
        }
        if ((tid & 31) == 0) {
            atomicAdd(&stats[oc], (double)s);
            atomicAdd(&stats[16 + oc], (double)q);
        }
    }
}

// ---------------- conv_s2_v9: plain-float input smem + register dup ---------------
// Halves input LDS bytes vs dup-smem (R11 ncu: L1 87.5% -> crossbar bound).
// Per (ic,k9): 2x LDS.128 + LDS.32 input, 9 pack movs, OCPT/2 wq LDS (broadcast),
// 3*4*(OCPT/2) FFMA2. Slot-offset loader + prologue prefetch + inlined BN finalize.
template <int CIN, int COUTT, int COUTB, int OCPT, int ICC, int MAXB>
__global__ void __launch_bounds__(128, MAXB) conv_s2_v9(
    const float* __restrict__ in, const float* __restrict__ wT,
    const float* __restrict__ bias,
    const double* __restrict__ statsPrev, const float* __restrict__ gPrev,
    const float* __restrict__ bePrev, float invN,
    float* __restrict__ out, double* __restrict__ stats,
    int Din, int Dout, int ntx, int nty) {
    constexpr int GROUPS = COUTB / OCPT;
    constexpr int THREADS = 32 * GROUPS;
    constexpr int NPAIR = OCPT / 2;
    constexpr int IZ = 9, IYE = 9, IX = 17, IXP = 20;   // plain floats, 20/row (16B-aligned)
    constexpr int NINF = ICC * IZ * IYE * IXP;
    constexpr int NSLOT = (NINF + THREADS - 1) / THREADS;
    constexpr int NW = COUTB * ICC * 27;
    static_assert(THREADS == 128, "tile mapping assumes 128 threads");
    static_assert((NPAIR & 1) == 0, "NPAIR must be even");

    extern __shared__ float sm[];
    float* sIn = sm;                 // NSLOT*THREADS floats (padded)
    float* sW  = sm + NSLOT * THREADS;
    __shared__ float bsum[COUTB], bsq[COUTB];
    __shared__ float sScale[CIN], sShift[CIN];

    int tid = threadIdx.x;
    int b = blockIdx.y;
    int ocBase = blockIdx.z * COUTB;
    int t = blockIdx.x;
    int tx = t % ntx, ty = (t / ntx) % nty, tz = t / (ntx * nty);

    int vt = tid & 31;
    int group = tid >> 5;
    int oxv = vt & 1;
    int oy  = (vt >> 1) & 3;
    int oz  = vt >> 3;

    bn_finalize_smem(statsPrev, gPrev, bePrev, invN, CIN, tid, sScale, sShift);

    int ginz = tz * 8 - 1;
    int giny = ty * 8 - 1;
    int ginx = tx * 16 - 1;

    const float* inB = in + (long long)b * CIN * Din * Din * Din;
    const int chanStride = Din * Din * Din;

    // per-slot packed offsets (once per block)
    int goff[NSLOT];
    {
        int i = tid;
#pragma unroll
        for (int s = 0; s < NSLOT; s++, i += THREADS) {
            int ix = i % IXP;
            int r  = i / IXP;
            int iy = r % IYE;
            int r2 = r / IYE;
            int iz = r2 % IZ;
            int icl = r2 / IZ;
            int gz = ginz + iz, gy = giny + iy, gx = ginx + ix;
            bool ok = (i < NINF) && (ix < IX) &&
                      ((unsigned)gz < (unsigned)Din) &&
                      ((unsigned)gy < (unsigned)Din) &&
                      ((unsigned)gx < (unsigned)Din);
            int off = ((icl * Din + gz) * Din + gy) * Din + gx;
            goff[s] = ok ? (off | (icl << 24)) : -1;
        }
    }

    u64t acc[NPAIR][4];
#pragma unroll
    for (int p = 0; p < NPAIR; p++)
#pragma unroll
        for (int u = 0; u < 4; u++) acc[p][u] = 0ULL;

    // prologue prefetch
    float pre[NSLOT];
#pragma unroll
    for (int s = 0; s < NSLOT; s++) {
        int pk = goff[s];
        pre[s] = (pk >= 0) ? __ldg(inB + (pk & 0x00FFFFFF)) : 0.f;
    }

#pragma unroll 1
    for (int c0 = 0; c0 < CIN; c0 += ICC) {
        __syncthreads();
#pragma unroll
        for (int s = 0; s < NSLOT; s++) {
            int pk = goff[s];
            float v = 0.f;
            if (pk >= 0) {
                int icl = pk >> 24;
                v = fmaxf(fmaf(pre[s], sScale[c0 + icl], sShift[c0 + icl]), 0.f);
            }
            sIn[s * THREADS + tid] = v;
        }
        {
            const float* srcw = wT + c0 * 27 * COUTT;
            if (COUTB == COUTT) {
#pragma unroll
                for (int i = tid * 4; i < NW; i += THREADS * 4)
                    *reinterpret_cast<float4*>(&sW[i]) =
                        *reinterpret_cast<const float4*>(&srcw[i]);
            } else {
#pragma unroll
                for (int i = tid * 4; i < NW; i += THREADS * 4) {
                    int ocl = i % COUTB;
                    int row = i / COUTB;
                    *reinterpret_cast<float4*>(&sW[i]) =
                        *reinterpret_cast<const float4*>(&srcw[row * COUTT + ocBase + ocl]);
                }
            }
        }
        __syncthreads();

        if (c0 + ICC < CIN) {
            const float* inC2 = inB + (c0 + ICC) * chanStride;
#pragma unroll
            for (int s = 0; s < NSLOT; s++) {
                int pk = goff[s];
                pre[s] = (pk >= 0) ? __ldg(inC2 + (pk & 0x00FFFFFF)) : 0.f;
            }
        }

#pragma unroll
        for (int ic = 0; ic < ICC; ic++) {
#pragma unroll
            for (int kd = 0; kd < 3; kd++)
#pragma unroll
                for (int kh = 0; kh < 3; kh++) {
                    const float* ip =
                        &sIn[((ic * IZ + (2 * oz + kd)) * IYE + (2 * oy + kh)) * IXP +
                             8 * oxv];
                    float4 va = *reinterpret_cast<const float4*>(ip);
                    float4 vb = *reinterpret_cast<const float4*>(ip + 4);
                    float v8 = ip[8];
                    u64t ivd[9];
                    ivd[0] = pack2f(va.x, va.x); ivd[1] = pack2f(va.y, va.y);
                    ivd[2] = pack2f(va.z, va.z); ivd[3] = pack2f(va.w, va.w);
                    ivd[4] = pack2f(vb.x, vb.x); ivd[5] = pack2f(vb.y, vb.y);
                    ivd[6] = pack2f(vb.z, vb.z); ivd[7] = pack2f(vb.w, vb.w);
                    ivd[8] = pack2f(v8, v8);
                    int k9 = kd * 3 + kh;
                    const float* wb_ = &sW[(ic * 27 + k9 * 3) * COUTB + group * OCPT];
#pragma unroll
                    for (int kw = 0; kw < 3; kw++) {
                        ulonglong2 wq[NPAIR / 2];
#pragma unroll
                        for (int pp = 0; pp < NPAIR / 2; pp++)
                            wq[pp] = *reinterpret_cast<const ulonglong2*>(
                                wb_ + kw * COUTB + pp * 4);
#pragma unroll
                        for (int u = 0; u < 4; u++) {
                            u64t iv = ivd[2 * u + kw];
#pragma unroll
                            for (int pp = 0; pp < NPAIR / 2; pp++) {
                                ffma2(acc[2 * pp][u], wq[pp].x, iv);
                                ffma2(acc[2 * pp + 1][u], wq[pp].y, iv);
                            }
                        }
                    }
                }
        }
    }

    int gz = tz * 4 + oz, gy = ty * 4 + oy;
    int gx = tx * 8 + oxv * 4;
#pragma unroll 1
    for (int p = 0; p < NPAIR; p++) {
        float o0[4], o1[4];
#pragma unroll
        for (int u = 0; u < 4; u++) unpack2f(acc[p][u], o0[u], o1[u]);
#pragma unroll
        for (int h = 0; h < 2; h++) {
            float* ov = h ? o1 : o0;
            int ocl = group * OCPT + 2 * p + h;
            int oc = ocBase + ocl;
            float bb = bias[oc];
            float a0 = ov[0] + bb, a1 = ov[1] + bb, a2 = ov[2] + bb, a3 = ov[3] + bb;
            *reinterpret_cast<float4*>(
                &out[(((b * COUTT + oc) * Dout + gz) * Dout + gy) * Dout + gx]) =
                make_float4(a0, a1, a2, a3);

            float s = a0 + a1 + a2 + a3;
            float q = a0 * a0 + a1 * a1 + a2 * a2 + a3 * a3;
#pragma unroll
            for (int off = 16; off > 0; off >>= 1) {
                s += __shfl_down_sync(0xffffffffu, s, off);
                q += __shfl_down_sync(0xffffffffu, q, off);
            }
            if (vt == 0) { bsum[ocl] = s; bsq[ocl] = q; }
        }
    }
    __syncthreads();
    if (tid < COUTB) {
        atomicAdd(&stats[ocBase + tid], (double)bsum[tid]);
        atomicAdd(&stats[COUTT + ocBase + tid], (double)bsq[tid]);
    }
}

// ---------------- old generic stride-2 conv (stage 4) + inline finalize ------------
template <int CIN, int COUTB, int OCPT>
__global__ void __launch_bounds__(128) conv_s2_kernel(
    const float* __restrict__ in, const float* __restrict__ w,
    const float* __restrict__ bias,
    const double* __restrict__ statsPrev, const float* __restrict__ gPrev,
    const float* __restrict__ bePrev, float invN,
    float* __restrict__ out, double* __restrict__ stats,
    int Din, int Dout, int ntile, int coutTot) {
    constexpr int ICC = 16;
    constexpr int NIN = ICC * 729;
    constexpr int NW  = COUTB * ICC * 27;
    extern __shared__ float sm[];
    float* sIn = sm;
    float* sW  = sm + NIN;
    __shared__ float bsum[COUTB], bsq[COUTB];
    __shared__ float sScale[CIN], sShift[CIN];

    int tid = threadIdx.x;
    int b = blockIdx.y;
    int ocBase = blockIdx.z * COUTB;
    int t = blockIdx.x;
    int tz = t / (ntile * ntile), ty = (t / ntile) % ntile, tx = t % ntile;
    int pair = tid & 31, group = tid >> 5;
    int oz = pair >> 3, oy = (pair >> 1) & 3, px = pair & 1;

    bn_finalize_smem(statsPrev, gPrev, bePrev, invN, CIN, tid, sScale, sShift);

    if (tid < COUTB) { bsum[tid] = 0.f; bsq[tid] = 0.f; }

    float acc0[OCPT], acc1[OCPT];
#pragma unroll
    for (int j = 0; j < OCPT; j++) { acc0[j] = 0.f; acc1[j] = 0.f; }

    for (int c0 = 0; c0 < CIN; c0 += ICC) {
        __syncthreads();
        for (int i = tid; i < NIN; i += 128) {
            int ic = i / 729, r = i % 729;
            int iz = r / 81, iy = (r / 9) % 9, ix = r % 9;
            int gz = tz * 8 - 1 + iz, gy = ty * 8 - 1 + iy, gx = tx * 8 - 1 + ix;
            float v = 0.f;
            if ((unsigned)gz < (unsigned)Din && (unsigned)gy < (unsigned)Din &&
                (unsigned)gx < (unsigned)Din) {
                v = in[(((b * CIN + c0 + ic) * Din + gz) * Din + gy) * Din + gx];
                v = fmaxf(fmaf(v, sScale[c0 + ic], sShift[c0 + ic]), 0.f);
            }
            sIn[i] = v;
        }
        for (int i = tid; i < NW; i += 128) {
            int ocl = i / (ICC * 27), r = i % (ICC * 27);
            sW[i] = w[((ocBase + ocl) * CIN + c0) * 27 + r];
        }
        __syncthreads();

#pragma unroll 1
        for (int ic = 0; ic < ICC; ic++) {
            const float* wrow = &sW[(group * OCPT) * ICC * 27 + ic * 27];
#pragma unroll
            for (int kd = 0; kd < 3; kd++)
#pragma unroll
                for (int kh = 0; kh < 3; kh++) {
                    int base = ((ic * 9 + (2 * oz + kd)) * 9 + (2 * oy + kh)) * 9 + 4 * px;
                    float ivs[5];
#pragma unroll
                    for (int u = 0; u < 5; u++) ivs[u] = sIn[base + u];
#pragma unroll
                    for (int kw = 0; kw < 3; kw++) {
#pragma unroll
                        for (int j = 0; j < OCPT; j++) {
                            float wv = wrow[j * ICC * 27 + (kd * 3 + kh) * 3 + kw];
                            acc0[j] = fmaf(ivs[kw], wv, acc0[j]);
                            acc1[j] = fmaf(ivs[kw + 2], wv, acc1[j]);
                        }
                    }
                }
        }
    }

    int gz = tz * 4 + oz, gy = ty * 4 + oy, gx = tx * 4 + 2 * px;
#pragma unroll
    for (int j = 0; j < OCPT; j++) {
        int oc = ocBase + group * OCPT + j;
        float bb = bias[oc];
        float o0 = acc0[j] + bb, o1 = acc1[j] + bb;
        *reinterpret_cast<float2*>(
            &out[(((b * coutTot + oc) * Dout + gz) * Dout + gy) * Dout + gx]) =
            make_float2(o0, o1);

        float s = o0 + o1, q = o0 * o0 + o1 * o1;
#pragma unroll
        for (int off = 16; off > 0; off >>= 1) {
            s += __shfl_down_sync(0xffffffffu, s, off);
            q += __shfl_down_sync(0xffffffffu, q, off);
        }
        if (pair == 0) {
            atomicAdd(&bsum[group * OCPT + j], s);
            atomicAdd(&bsq[group * OCPT + j], q);
        }
    }
    __syncthreads();
    if (tid < COUTB) {
        atomicAdd(&stats[ocBase + tid], (double)bsum[tid]);
        atomicAdd(&stats[coutTot + ocBase + tid], (double)bsq[tid]);
    }
}

// ---------------- heads: BN finalize + 12 dot products + matrix composition --------
__device__ __forceinline__ void ident4(float* M) {
#pragma unroll
    for (int i = 0; i < 16; i++) M[i] = (i % 5 == 0) ? 1.f : 0.f;
}
__device__ __forceinline__ void mm4(const float* A, const float* B, float* C) {
#pragma unroll
    for (int i = 0; i < 4; i++)
#pragma unroll
        for (int j = 0; j < 4; j++)
            C[i * 4 + j] = A[i * 4 + 0] * B[0 + j] + A[i * 4 + 1] * B[4 + j] +
                           A[i * 4 + 2] * B[8 + j] + A[i * 4 + 3] * B[12 + j];
}

__global__ void __launch_bounds__(256) heads_kernel(
    const float* __restrict__ xs,
    const double* __restrict__ statsPrev, const float* __restrict__ gPrev,
    const float* __restrict__ bePrev, float invN,
    const float* __restrict__ tw, const float* __restrict__ tb,
    const float* __restrict__ rw, const float* __restrict__ rb,
    const float* __restrict__ sw_, const float* __restrict__ sb_,
    const float* __restrict__ shw, const float* __restrict__ shb,
    float* __restrict__ theta) {
    __shared__ float red[12 * 256];
    __shared__ float ssc[64], ssh[64];
    int b = blockIdx.x, tid = threadIdx.x;
    bn_finalize_smem(statsPrev, gPrev, bePrev, invN, 64, tid, ssc, ssh);
    __syncthreads();
    float p[12];
#pragma unroll
    for (int r = 0; r < 12; r++) p[r] = 0.f;
    for (int i = tid; i < 4096; i += 256) {
        int c = i >> 6;
        float v = fmaxf(fmaf(xs[b * 4096 + i], ssc[c], ssh[c]), 0.f);
#pragma unroll
        for (int r = 0; r < 3; r++) {
            p[r]     = fmaf(v, tw[r * 4096 + i], p[r]);
            p[3 + r] = fmaf(v, rw[r * 4096 + i], p[3 + r]);
            p[6 + r] = fmaf(v, sw_[r * 4096 + i], p[6 + r]);
            p[9 + r] = fmaf(v, shw[r * 4096 + i], p[9 + r]);
        }
    }
#pragma unroll
    for (int r = 0; r < 12; r++) red[r * 256 + tid] = p[r];
    __syncthreads();
    for (int s = 128; s > 0; s >>= 1) {
        if (tid < s)
#pragma unroll
            for (int r = 0; r < 12; r++) red[r * 256 + tid] += red[r * 256 + tid + s];
        __syncthreads();
    }
    if (tid == 0) {
        const float PI4 = 0.7853981633974483f;
        float tr[3], ro[3], scp[3], shp[3];
#pragma unroll
        for (int r = 0; r < 3; r++) {
            tr[r]  = tanhf(red[r * 256] + tb[r]) * 0.1f;
            ro[r]  = tanhf(red[(3 + r) * 256] + rb[r]) * PI4;
            scp[r] = tanhf(red[(6 + r) * 256] + sb_[r]) * 0.2f;
            shp[r] = tanhf(red[(9 + r) * 256] + shb[r]) * PI4;
        }
        float c0 = cosf(ro[0]), s0 = sinf(ro[0]);
        float c1 = cosf(ro[1]), s1 = sinf(ro[1]);
        float c2 = cosf(ro[2]), s2 = sinf(ro[2]);
        float cs0 = cosf(shp[0]), ss0 = sinf(shp[0]);
        float cs1 = cosf(shp[1]), ss1 = sinf(shp[1]);
        float cs2 = cosf(shp[2]), ss2 = sinf(shp[2]);

        float T[16], R1[16], R2[16], R3[16], S[16], H1[16], H2[16], H3[16];
        float R[16], Sh[16], ShT[16], A[16], B[16];
        ident4(T);  T[3] = tr[0]; T[7] = tr[1]; T[11] = tr[2];
        ident4(R1); R1[0] = c0; R1[1] = -s0; R1[4] = s0; R1[5] = c0;
        ident4(R2); R2[5] = c1; R2[6] = -s1; R2[9] = s1; R2[10] = c1;
        ident4(R3); R3[0] = c2; R3[1] = -s2; R3[4] = s2; R3[5] = c2;
        ident4(S);  S[0] = expf(scp[0]); S[5] = expf(scp[1]); S[10] = expf(scp[2]);
        ident4(H1); H1[5] = cs0; H1[6] = -ss0; H1[9] = ss0; H1[10] = cs0;
        ident4(H2); H2[0] = cs1; H2[2] = ss1; H2[8] = -ss1; H2[10] = cs1;
        ident4(H3); H3[0] = cs2; H3[1] = -ss2; H3[4] = ss2; H3[5] = cs2;

        mm4(R1, R2, A); mm4(A, R3, R);
        mm4(H1, H2, A); mm4(A, H3, Sh);
#pragma unroll
        for (int i = 0; i < 4; i++)
#pragma unroll
            for (int j = 0; j < 4; j++) ShT[i * 4 + j] = Sh[j * 4 + i];
        mm4(Sh, S, A); mm4(A, ShT, B); mm4(B, R, A); mm4(A, T, B);
#pragma unroll
        for (int i = 0; i < 12; i++) theta[b * 12 + i] = B[i];
    }
}

// ---------------- trilinear grid sample (zero padding, clamped gather) ----------------
__global__ void __launch_bounds__(256) sampler_kernel(
    const float* __restrict__ x, const float* __restrict__ theta,
    float* __restrict__ out) {
    int idx = blockIdx.x * 256 + threadIdx.x;
    int b = idx >> 18;
    int r = idx & 262143;
    int z = r >> 12, y = (r >> 6) & 63, xq = r & 63;
    const float st = 2.f / 63.f;
    float xx = fmaf((float)xq, st, -1.f);
    float yy = fmaf((float)y, st, -1.f);
    float zz = fmaf((float)z, st, -1.f);
    const float* th = &theta[b * 12];
    float g0 = th[0] * xx + th[1] * yy + th[2] * zz + th[3];
    float g1 = th[4] * xx + th[5] * yy + th[6] * zz + th[7];
    float g2 = th[8] * xx + th[9] * yy + th[10] * zz + th[11];
    float fx = ((g0 + 1.f) * 64.f - 1.f) * 0.5f;
    float fy = ((g1 + 1.f) * 64.f - 1.f) * 0.5f;
    float fz = ((g2 + 1.f) * 64.f - 1.f) * 0.5f;
    float x0f = floorf(fx), y0f = floorf(fy), z0f = floorf(fz);
    int x0 = (int)x0f, y0 = (int)y0f, z0 = (int)z0f;
    float wx1 = fx - x0f, wx0 = 1.f - wx1;
    float wy1 = fy - y0f, wy0 = 1.f - wy1;
    float wz1 = fz - z0f, wz0 = 1.f - wz1;
    const float* xb = &x[b << 18];
    float acc = 0.f;
#pragma unroll
    for (int dz = 0; dz < 2; dz++) {
        int zc = z0 + dz;
        float wz = dz ? wz1 : wz0;
        bool vz = (zc >= 0 && zc < 64);
        int zi = min(max(zc, 0), 63);
#pragma unroll
        for (int dy = 0; dy < 2; dy++) {
            int yc = y0 + dy;
            float wy = dy ? wy1 : wy0;
            bool vy = vz && (yc >= 0 && yc < 64);
            int yi = min(max(yc, 0), 63);
#pragma unroll
            for (int dx = 0; dx < 2; dx++) {
                int xc = x0 + dx;
                float wgt = wz * wy * (dx ? wx1 : wx0);
                bool v = vy && (xc >= 0 && xc < 64);
                int xi = min(max(xc, 0), 63);
                float val = xb[(zi * 64 + yi) * 64 + xi];
                acc += v ? val * wgt : 0.f;
            }
        }
    }
    out[idx] = acc;
}

// ---------------- launch ----------------
extern "C" void kernel_launch(void* const* d_in, const int* in_sizes, int n_in,
                              void* d_out, int out_size) {
    const float* x    = (const float*)d_in[0];
    const float* w00  = (const float*)d_in[1];
    const float* b00  = (const float*)d_in[2];
    const float* g00  = (const float*)d_in[3];
    const float* be00 = (const float*)d_in[4];
    const float* w0   = (const float*)d_in[5];
    const float* b0   = (const float*)d_in[6];
    const float* g0   = (const float*)d_in[7];
    const float* be0  = (const float*)d_in[8];
    const float* w1   = (const float*)d_in[9];
    const float* b1   = (const float*)d_in[10];
    const float* g1   = (const float*)d_in[11];
    const float* be1  = (const float*)d_in[12];
    const float* w2   = (const float*)d_in[13];
    const float* b2   = (const float*)d_in[14];
    const float* g2   = (const float*)d_in[15];
    const float* be2  = (const float*)d_in[16];
    const float* w3   = (const float*)d_in[17];
    const float* b3   = (const float*)d_in[18];
    const float* g3   = (const float*)d_in[19];
    const float* be3  = (const float*)d_in[20];
    const float* tw   = (const float*)d_in[21];
    const float* tb   = (const float*)d_in[22];
    const float* rw   = (const float*)d_in[23];
    const float* rb   = (const float*)d_in[24];
    const float* sw   = (const float*)d_in[25];
    const float* sb   = (const float*)d_in[26];
    const float* shw  = (const float*)d_in[27];
    const float* shb  = (const float*)d_in[28];

    float *buf0, *buf1, *buf2, *buf3, *buf4, *theta;
    float *wT0, *wT1, *wT2;
    double* stats;
    cudaGetSymbolAddress((void**)&buf0, g_buf0);
    cudaGetSymbolAddress((void**)&buf1, g_buf1);
    cudaGetSymbolAddress((void**)&buf2, g_buf2);
    cudaGetSymbolAddress((void**)&buf3, g_buf3);
    cudaGetSymbolAddress((void**)&buf4, g_buf4);
    cudaGetSymbolAddress((void**)&stats, g_stats);
    cudaGetSymbolAddress((void**)&theta, g_theta);
    cudaGetSymbolAddress((void**)&wT0, g_wT0);
    cudaGetSymbolAddress((void**)&wT1, g_wT1);
    cudaGetSymbolAddress((void**)&wT2, g_wT2);

    // v9 smem: input NSLOT(26)*128*4 = 13312 B + weights COUTB*2*27*4
    const int SM_S1 = 26 * 128 * 4 + 32 * 2 * 27 * 4;  // 20224
    const int SM_S2 = 26 * 128 * 4 + 64 * 2 * 27 * 4;  // 27136
    const int SM_S3 = 26 * 128 * 4 + 32 * 2 * 27 * 4;  // 20224
    const int SM_L4 = (16 * 729 + 16 * 16 * 27) * 4;   // 74304 (stage 4)
    cudaFuncSetAttribute(conv_s2_v9<16, 32, 32, 8, 2, 4>,
                         cudaFuncAttributeMaxDynamicSharedMemorySize, SM_S1);
    cudaFuncSetAttribute(conv_s2_v9<32, 64, 64, 16, 2, 3>,
                         cudaFuncAttributeMaxDynamicSharedMemorySize, SM_S2);
    cudaFuncSetAttribute(conv_s2_v9<64, 64, 32, 8, 2, 4>,
                         cudaFuncAttributeMaxDynamicSharedMemorySize, SM_S3);
    cudaFuncSetAttribute(conv_s2_kernel<64, 16, 4>,
                         cudaFuncAttributeMaxDynamicSharedMemorySize, SM_L4);

    // 1: prep (zero stats + all weight transposes)
    prep_kernel<<<702, 256>>>(w0, w1, w2, wT0, wT1, wT2, stats);

    // 2: conv00 1->16, 64^3
    conv00_v2<<<dim3(512, 16), 128>>>(x, w00, b00, buf0, stats + 0);

    // 3: stage 1: 16->32, 64^3 -> 32^3; 256 tiles
    conv_s2_v9<16, 32, 32, 8, 2, 4><<<dim3(256, 16, 1), 128, SM_S1>>>(
        buf0, wT0, b0, stats + 0, g00, be00, 1.f / 4194304.f,
        buf1, stats + 32, 64, 32, 4, 8);

    // 4: stage 2: 32->64, 32^3 -> 16^3; 32 tiles, full 64 oc, OCPT=16 -> 512 blocks
    conv_s2_v9<32, 64, 64, 16, 2, 3><<<dim3(32, 16, 1), 128, SM_S2>>>(
        buf1, wT1, b1, stats + 32, g0, be0, 1.f / 524288.f,
        buf2, stats + 96, 32, 16, 2, 4);

    // 5: stage 3: 64->64, 16^3 -> 8^3; 4 tiles x oc-split z=2 -> 128 blocks
    conv_s2_v9<64, 64, 32, 8, 2, 4><<<dim3(4, 16, 2), 128, SM_S3>>>(
        buf2, wT2, b2, stats + 96, g1, be1, 1.f / 65536.f,
        buf3, stats + 224, 16, 8, 1, 2);

    // 6: stage 4: 64->64, 8^3 -> 4^3 (tiny; old kernel, oc split z=4)
    conv_s2_kernel<64, 16, 4><<<dim3(1, 16, 4), 128, SM_L4>>>(
        buf3, w3, b3, stats + 224, g2, be2, 1.f / 8192.f,
        buf4, stats + 352, 8, 4, 1, 64);

    // 7: heads (inlines stage-4 BN finalize)
    heads_kernel<<<16, 256>>>(buf4, stats + 352, g3, be3, 1.f / 1024.f,
                              tw, tb, rw, rb, sw, sb, shw, shb, theta);

    // 8: grid sample
    sampler_kernel<<<16384, 256>>>(x, theta, (float*)d_out);
}

// round 13
// speedup vs baseline: 1.1272x; 1.0339x over previous
#include <cuda_runtime.h>
#include <math.h>

// ---------------- packed f32x2 helpers (sm_103a FFMA2 path) ----------------
typedef unsigned long long u64t;
__device__ __forceinline__ u64t pack2f(float lo, float hi) {
    u64t r;
    asm("mov.b64 %0, {%1, %2};" : "=l"(r)
        : "r"(__float_as_uint(lo)), "r"(__float_as_uint(hi)));
    return r;
}
__device__ __forceinline__ void ffma2(u64t& d, u64t a, u64t b) {
    asm("fma.rn.f32x2 %0, %1, %2, %0;" : "+l"(d) : "l"(a), "l"(b));
}
__device__ __forceinline__ void unpack2f(u64t v, float& lo, float& hi) {
    unsigned ulo, uhi;
    asm("mov.b64 {%0, %1}, %2;" : "=r"(ulo), "=r"(uhi) : "l"(v));
    lo = __uint_as_float(ulo);
    hi = __uint_as_float(uhi);
}

// ---------------- persistent device scratch ----------------
__device__ float  g_buf0[16u*16u*64u*64u*64u];
__device__ float  g_buf1[16u*32u*32u*32u*32u];
__device__ float  g_buf2[16u*64u*16u*16u*16u];
__device__ float  g_buf3[16u*64u*8u*8u*8u];
__device__ float  g_buf4[16u*64u*4u*4u*4u];
__device__ double g_stats[480];
__device__ float  g_theta[16*12];
__device__ float  g_wT0[32*16*27];
__device__ float  g_wT1[64*32*27];
__device__ float  g_wT2[64*64*27];

// ---------------- prep: zero stats + all three weight transposes ----------------
__global__ void prep_kernel(const float* __restrict__ w0, const float* __restrict__ w1,
                            const float* __restrict__ w2,
                            float* __restrict__ wT0, float* __restrict__ wT1,
                            float* __restrict__ wT2, double* __restrict__ stats) {
    int i = blockIdx.x * 256 + threadIdx.x;
    if (blockIdx.x == 0) {
        for (int k = threadIdx.x; k < 480; k += 256) stats[k] = 0.0;
    }
    if (i < 13824) {                       // w0: cout=32, cin27=432
        int oc = i & 31, icr = i >> 5;
        wT0[i] = w0[oc * 432 + icr];
    } else if (i < 69120) {                // w1: cout=64, cin27=864
        int j = i - 13824;
        int oc = j & 63, icr = j >> 6;
        wT1[j] = w1[oc * 864 + icr];
    } else if (i < 179712) {               // w2: cout=64, cin27=1728
        int j = i - 69120;
        int oc = j & 63, icr = j >> 6;
        wT2[j] = w2[oc * 1728 + icr];
    }
}

// ---------------- BN finalize (inline device helper) ----------------
__device__ __forceinline__ void bn_finalize_smem(
    const double* __restrict__ stats_prev, const float* __restrict__ g_prev,
    const float* __restrict__ be_prev, float invN, int C, int tid,
    float* sScale, float* sShift) {
    if (tid < C) {
        double mean = stats_prev[tid] * (double)invN;
        double var  = stats_prev[C + tid] * (double)invN - mean * mean;
        float a = g_prev[tid] * (float)(1.0 / sqrt(var + 1e-5));
        sScale[tid] = a;
        sShift[tid] = be_prev[tid] - (float)mean * a;
    }
}

// ---------------- conv00 v2: 1->16 ch, stride 1, pad 1, 64^3, FFMA2 ----------------
__global__ void __launch_bounds__(128) conv00_v2(
    const float* __restrict__ x, const float* __restrict__ w,
    const float* __restrict__ bias, float* __restrict__ out,
    double* __restrict__ stats) {
    __shared__ float sIn[1000];
    __shared__ float sWd[864];

    int tid = threadIdx.x;
    int b = blockIdx.y;
    int t = blockIdx.x;
    int tz = t >> 6, ty = (t >> 3) & 7, tx = t & 7;

    for (int i = tid; i < 1000; i += 128) {
        int iz = i / 100, iy = (i / 10) % 10, ix = i % 10;
        int gz = tz * 8 - 1 + iz, gy = ty * 8 - 1 + iy, gx = tx * 8 - 1 + ix;
        float v = 0.f;
        if ((unsigned)gz < 64u && (unsigned)gy < 64u && (unsigned)gx < 64u)
            v = x[((b * 64 + gz) * 64 + gy) * 64 + gx];
        sIn[i] = v;
    }
    for (int i = tid; i < 432; i += 128) {
        int k = i >> 4, oc = i & 15;
        float wv = w[oc * 27 + k];
        sWd[k * 32 + oc * 2]     = wv;
        sWd[k * 32 + oc * 2 + 1] = wv;
    }
    __syncthreads();

    int sz = tid >> 4, sy = (tid >> 1) & 7, sx = tid & 1;

    u64t acc[16][2];
#pragma unroll
    for (int oc = 0; oc < 16; oc++) { acc[oc][0] = 0ULL; acc[oc][1] = 0ULL; }

#pragma unroll
    for (int kd = 0; kd < 3; kd++)
#pragma unroll
        for (int kh = 0; kh < 3; kh++) {
            int base = (sz + kd) * 100 + (sy + kh) * 10 + sx * 4;
            float i0 = sIn[base], i1 = sIn[base + 1], i2 = sIn[base + 2];
            float i3 = sIn[base + 3], i4 = sIn[base + 4], i5 = sIn[base + 5];
            u64t P[5];
            P[0] = pack2f(i0, i1); P[1] = pack2f(i1, i2); P[2] = pack2f(i2, i3);
            P[3] = pack2f(i3, i4); P[4] = pack2f(i4, i5);
            int k9 = kd * 3 + kh;
#pragma unroll
            for (int kw = 0; kw < 3; kw++) {
                const u64t* wrow =
                    reinterpret_cast<const u64t*>(&sWd[(k9 * 3 + kw) * 32]);
#pragma unroll
                for (int oc = 0; oc < 16; oc++) {
                    u64t wp = wrow[oc];
                    ffma2(acc[oc][0], P[kw], wp);
                    ffma2(acc[oc][1], P[kw + 2], wp);
                }
            }
        }

    int gz = tz * 8 + sz, gy = ty * 8 + sy, gx = tx * 8 + sx * 4;
#pragma unroll 1
    for (int oc = 0; oc < 16; oc++) {
        float a0, a1, a2, a3;
        unpack2f(acc[oc][0], a0, a1);
        unpack2f(acc[oc][1], a2, a3);
        float bb = bias[oc];
        a0 += bb; a1 += bb; a2 += bb; a3 += bb;
        *reinterpret_cast<float4*>(&out[(((b * 16 + oc) * 64 + gz) * 64 + gy) * 64 + gx]) =
            make_float4(a0, a1, a2, a3);

        float s = a0 + a1 + a2 + a3;
        float q = a0 * a0 + a1 * a1 + a2 * a2 + a3 * a3;
#pragma unroll
        for (int off = 16; off > 0; off >>= 1) {
            s += __shfl_down_sync(0xffffffffu, s, off);
            q += __shfl_down_sync(0xffffffffu, q, off);
        }
        if ((tid & 31) == 0) {
            atomicAdd(&stats[oc], (double)s);
            atomicAdd(&stats[16 + oc], (double)q);
        }
    }
}

// ---------------- conv_s2_v10: ICC=1, no prefetch, minimal registers --------------
// Plain-float input smem (36 B/lane per k9), register-dup packs, slot offsets.
// ICC=1: loader has NO channel extraction; BN is 2 broadcast scalars per c0.
template <int CIN, int COUTT, int COUTB, int OCPT, int MAXB>
__global__ void __launch_bounds__(128, MAXB) conv_s2_v10(
    const float* __restrict__ in, const float* __restrict__ wT,
    const float* __restrict__ bias,
    const double* __restrict__ statsPrev, const float* __restrict__ gPrev,
    const float* __restrict__ bePrev, float invN,
    float* __restrict__ out, double* __restrict__ stats,
    int Din, int Dout, int ntx, int nty) {
    constexpr int GROUPS = COUTB / OCPT;
    constexpr int THREADS = 32 * GROUPS;
    constexpr int NPAIR = OCPT / 2;
    constexpr int IZ = 9, IYE = 9, IX = 17, IXP = 20;
    constexpr int NINF = IZ * IYE * IXP;                 // 1620 floats (1 channel)
    constexpr int NSLOT = (NINF + THREADS - 1) / THREADS;  // 13
    constexpr int NW = COUTB * 27;
    static_assert(THREADS == 128, "tile mapping assumes 128 threads");
    static_assert((NPAIR & 1) == 0, "NPAIR must be even");

    extern __shared__ float sm[];
    float* sIn = sm;                  // NSLOT*THREADS floats
    float* sW  = sm + NSLOT * THREADS;
    __shared__ float bsum[COUTB], bsq[COUTB];
    __shared__ float sScale[CIN], sShift[CIN];

    int tid = threadIdx.x;
    int b = blockIdx.y;
    int ocBase = blockIdx.z * COUTB;
    int t = blockIdx.x;
    int tx = t % ntx, ty = (t / ntx) % nty, tz = t / (ntx * nty);

    int vt = tid & 31;
    int group = tid >> 5;
    int oxv = vt & 1;
    int oy  = (vt >> 1) & 3;
    int oz  = vt >> 3;

    bn_finalize_smem(statsPrev, gPrev, bePrev, invN, CIN, tid, sScale, sShift);

    int ginz = tz * 8 - 1;
    int giny = ty * 8 - 1;
    int ginx = tx * 16 - 1;

    const float* inB = in + (long long)b * CIN * Din * Din * Din;
    const int chanStride = Din * Din * Din;

    // per-slot offsets (once per block; ICC=1 so no channel component)
    int goff[NSLOT];
    {
        int i = tid;
#pragma unroll
        for (int s = 0; s < NSLOT; s++, i += THREADS) {
            int ix = i % IXP;
            int r  = i / IXP;
            int iy = r % IYE;
            int iz = r / IYE;
            int gz = ginz + iz, gy = giny + iy, gx = ginx + ix;
            bool ok = (i < NINF) && (ix < IX) &&
                      ((unsigned)gz < (unsigned)Din) &&
                      ((unsigned)gy < (unsigned)Din) &&
                      ((unsigned)gx < (unsigned)Din);
            goff[s] = ok ? ((gz * Din + gy) * Din + gx) : -1;
        }
    }

    u64t acc[NPAIR][4];
#pragma unroll
    for (int p = 0; p < NPAIR; p++)
#pragma unroll
        for (int u = 0; u < 4; u++) acc[p][u] = 0ULL;

#pragma unroll 1
    for (int c0 = 0; c0 < CIN; c0++) {
        __syncthreads();   // prev compute done; also covers sScale init at c0=0
        float sc = sScale[c0], sh = sShift[c0];
        const float* inC = inB + c0 * chanStride;
#pragma unroll
        for (int s = 0; s < NSLOT; s++) {
            int pk = goff[s];
            float v = 0.f;
            if (pk >= 0) v = fmaxf(fmaf(__ldg(inC + pk), sc, sh), 0.f);
            sIn[s * THREADS + tid] = v;
        }
        {
            const float* srcw = wT + c0 * 27 * COUTT;
            if (COUTB == COUTT) {
#pragma unroll
                for (int i = tid * 4; i < NW; i += THREADS * 4)
                    *reinterpret_cast<float4*>(&sW[i]) =
                        *reinterpret_cast<const float4*>(&srcw[i]);
            } else {
#pragma unroll
                for (int i = tid * 4; i < NW; i += THREADS * 4) {
                    int ocl = i % COUTB;
                    int row = i / COUTB;
                    *reinterpret_cast<float4*>(&sW[i]) =
                        *reinterpret_cast<const float4*>(&srcw[row * COUTT + ocBase + ocl]);
                }
            }
        }
        __syncthreads();

#pragma unroll
        for (int kd = 0; kd < 3; kd++)
#pragma unroll
            for (int kh = 0; kh < 3; kh++) {
                const float* ip =
                    &sIn[((2 * oz + kd) * IYE + (2 * oy + kh)) * IXP + 8 * oxv];
                float4 va = *reinterpret_cast<const float4*>(ip);
                float4 vb = *reinterpret_cast<const float4*>(ip + 4);
                float v8 = ip[8];
                u64t ivd[9];
                ivd[0] = pack2f(va.x, va.x); ivd[1] = pack2f(va.y, va.y);
                ivd[2] = pack2f(va.z, va.z); ivd[3] = pack2f(va.w, va.w);
                ivd[4] = pack2f(vb.x, vb.x); ivd[5] = pack2f(vb.y, vb.y);
                ivd[6] = pack2f(vb.z, vb.z); ivd[7] = pack2f(vb.w, vb.w);
                ivd[8] = pack2f(v8, v8);
                int k9 = kd * 3 + kh;
                const float* wb_ = &sW[(k9 * 3) * COUTB + group * OCPT];
#pragma unroll
                for (int kw = 0; kw < 3; kw++) {
                    ulonglong2 wq[NPAIR / 2];
#pragma unroll
                    for (int pp = 0; pp < NPAIR / 2; pp++)
                        wq[pp] = *reinterpret_cast<const ulonglong2*>(
                            wb_ + kw * COUTB + pp * 4);
#pragma unroll
                    for (int u = 0; u < 4; u++) {
                        u64t iv = ivd[2 * u + kw];
#pragma unroll
                        for (int pp = 0; pp < NPAIR / 2; pp++) {
                            ffma2(acc[2 * pp][u], wq[pp].x, iv);
                            ffma2(acc[2 * pp + 1][u], wq[pp].y, iv);
                        }
                    }
                }
            }
    }

    int gz = tz * 4 + oz, gy = ty * 4 + oy;
    int gx = tx * 8 + oxv * 4;
#pragma unroll 1
    for (int p = 0; p < NPAIR; p++) {
        float o0[4], o1[4];
#pragma unroll
        for (int u = 0; u < 4; u++) unpack2f(acc[p][u], o0[u], o1[u]);
#pragma unroll
        for (int h = 0; h < 2; h++) {
            float* ov = h ? o1 : o0;
            int ocl = group * OCPT + 2 * p + h;
            int oc = ocBase + ocl;
            float bb = bias[oc];
            float a0 = ov[0] + bb, a1 = ov[1] + bb, a2 = ov[2] + bb, a3 = ov[3] + bb;
            *reinterpret_cast<float4*>(
                &out[(((b * COUTT + oc) * Dout + gz) * Dout + gy) * Dout + gx]) =
                make_float4(a0, a1, a2, a3);

            float s = a0 + a1 + a2 + a3;
            float q = a0 * a0 + a1 * a1 + a2 * a2 + a3 * a3;
#pragma unroll
            for (int off = 16; off > 0; off >>= 1) {
                s += __shfl_down_sync(0xffffffffu, s, off);
                q += __shfl_down_sync(0xffffffffu, q, off);
            }
            if (vt == 0) { bsum[ocl] = s; bsq[ocl] = q; }
        }
    }
    __syncthreads();
    if (tid < COUTB) {
        atomicAdd(&stats[ocBase + tid], (double)bsum[tid]);
        atomicAdd(&stats[COUTT + ocBase + tid], (double)bsq[tid]);
    }
}

// ---------------- old generic stride-2 conv (stage 4) + inline finalize ------------
template <int CIN, int COUTB, int OCPT>
__global__ void __launch_bounds__(128) conv_s2_kernel(
    const float* __restrict__ in, const float* __restrict__ w,
    const float* __restrict__ bias,
    const double* __restrict__ statsPrev, const float* __restrict__ gPrev,
    const float* __restrict__ bePrev, float invN,
    float* __restrict__ out, double* __restrict__ stats,
    int Din, int Dout, int ntile, int coutTot) {
    constexpr int ICC = 16;
    constexpr int NIN = ICC * 729;
    constexpr int NW  = COUTB * ICC * 27;
    extern __shared__ float sm[];
    float* sIn = sm;
    float* sW  = sm + NIN;
    __shared__ float bsum[COUTB], bsq[COUTB];
    __shared__ float sScale[CIN], sShift[CIN];

    int tid = threadIdx.x;
    int b = blockIdx.y;
    int ocBase = blockIdx.z * COUTB;
    int t = blockIdx.x;
    int tz = t / (ntile * ntile), ty = (t / ntile) % ntile, tx = t % ntile;
    int pair = tid & 31, group = tid >> 5;
    int oz = pair >> 3, oy = (pair >> 1) & 3, px = pair & 1;

    bn_finalize_smem(statsPrev, gPrev, bePrev, invN, CIN, tid, sScale, sShift);

    if (tid < COUTB) { bsum[tid] = 0.f; bsq[tid] = 0.f; }

    float acc0[OCPT], acc1[OCPT];
#pragma unroll
    for (int j = 0; j < OCPT; j++) { acc0[j] = 0.f; acc1[j] = 0.f; }

    for (int c0 = 0; c0 < CIN; c0 += ICC) {
        __syncthreads();
        for (int i = tid; i < NIN; i += 128) {
            int ic = i / 729, r = i % 729;
            int iz = r / 81, iy = (r / 9) % 9, ix = r % 9;
            int gz = tz * 8 - 1 + iz, gy = ty * 8 - 1 + iy, gx = tx * 8 - 1 + ix;
            float v = 0.f;
            if ((unsigned)gz < (unsigned)Din && (unsigned)gy < (unsigned)Din &&
                (unsigned)gx < (unsigned)Din) {
                v = in[(((b * CIN + c0 + ic) * Din + gz) * Din + gy) * Din + gx];
                v = fmaxf(fmaf(v, sScale[c0 + ic], sShift[c0 + ic]), 0.f);
            }
            sIn[i] = v;
        }
        for (int i = tid; i < NW; i += 128) {
            int ocl = i / (ICC * 27), r = i % (ICC * 27);
            sW[i] = w[((ocBase + ocl) * CIN + c0) * 27 + r];
        }
        __syncthreads();

#pragma unroll 1
        for (int ic = 0; ic < ICC; ic++) {
            const float* wrow = &sW[(group * OCPT) * ICC * 27 + ic * 27];
#pragma unroll
            for (int kd = 0; kd < 3; kd++)
#pragma unroll
                for (int kh = 0; kh < 3; kh++) {
                    int base = ((ic * 9 + (2 * oz + kd)) * 9 + (2 * oy + kh)) * 9 + 4 * px;
                    float ivs[5];
#pragma unroll
                    for (int u = 0; u < 5; u++) ivs[u] = sIn[base + u];
#pragma unroll
                    for (int kw = 0; kw < 3; kw++) {
#pragma unroll
                        for (int j = 0; j < OCPT; j++) {
                            float wv = wrow[j * ICC * 27 + (kd * 3 + kh) * 3 + kw];
                            acc0[j] = fmaf(ivs[kw], wv, acc0[j]);
                            acc1[j] = fmaf(ivs[kw + 2], wv, acc1[j]);
                        }
                    }
                }
        }
    }

    int gz = tz * 4 + oz, gy = ty * 4 + oy, gx = tx * 4 + 2 * px;
#pragma unroll
    for (int j = 0; j < OCPT; j++) {
        int oc = ocBase + group * OCPT + j;
        float bb = bias[oc];
        float o0 = acc0[j] + bb, o1 = acc1[j] + bb;
        *reinterpret_cast<float2*>(
            &out[(((b * coutTot + oc) * Dout + gz) * Dout + gy) * Dout + gx]) =
            make_float2(o0, o1);

        float s = o0 + o1, q = o0 * o0 + o1 * o1;
#pragma unroll
        for (int off = 16; off > 0; off >>= 1) {
            s += __shfl_down_sync(0xffffffffu, s, off);
            q += __shfl_down_sync(0xffffffffu, q, off);
        }
        if (pair == 0) {
            atomicAdd(&bsum[group * OCPT + j], s);
            atomicAdd(&bsq[group * OCPT + j], q);
        }
    }
    __syncthreads();
    if (tid < COUTB) {
        atomicAdd(&stats[ocBase + tid], (double)bsum[tid]);
        atomicAdd(&stats[coutTot + ocBase + tid], (double)bsq[tid]);
    }
}

// ---------------- heads: BN finalize + 12 dot products + matrix composition --------
__device__ __forceinline__ void ident4(float* M) {
#pragma unroll
    for (int i = 0; i < 16; i++) M[i] = (i % 5 == 0) ? 1.f : 0.f;
}
__device__ __forceinline__ void mm4(const float* A, const float* B, float* C) {
#pragma unroll
    for (int i = 0; i < 4; i++)
#pragma unroll
        for (int j = 0; j < 4; j++)
            C[i * 4 + j] = A[i * 4 + 0] * B[0 + j] + A[i * 4 + 1] * B[4 + j] +
                           A[i * 4 + 2] * B[8 + j] + A[i * 4 + 3] * B[12 + j];
}

__global__ void __launch_bounds__(256) heads_kernel(
    const float* __restrict__ xs,
    const double* __restrict__ statsPrev, const float* __restrict__ gPrev,
    const float* __restrict__ bePrev, float invN,
    const float* __restrict__ tw, const float* __restrict__ tb,
    const float* __restrict__ rw, const float* __restrict__ rb,
    const float* __restrict__ sw_, const float* __restrict__ sb_,
    const float* __restrict__ shw, const float* __restrict__ shb,
    float* __restrict__ theta) {
    __shared__ float red[12 * 256];
    __shared__ float ssc[64], ssh[64];
    int b = blockIdx.x, tid = threadIdx.x;
    bn_finalize_smem(statsPrev, gPrev, bePrev, invN, 64, tid, ssc, ssh);
    __syncthreads();
    float p[12];
#pragma unroll
    for (int r = 0; r < 12; r++) p[r] = 0.f;
    for (int i = tid; i < 4096; i += 256) {
        int c = i >> 6;
        float v = fmaxf(fmaf(xs[b * 4096 + i], ssc[c], ssh[c]), 0.f);
#pragma unroll
        for (int r = 0; r < 3; r++) {
            p[r]     = fmaf(v, tw[r * 4096 + i], p[r]);
            p[3 + r] = fmaf(v, rw[r * 4096 + i], p[3 + r]);
            p[6 + r] = fmaf(v, sw_[r * 4096 + i], p[6 + r]);
            p[9 + r] = fmaf(v, shw[r * 4096 + i], p[9 + r]);
        }
    }
#pragma unroll
    for (int r = 0; r < 12; r++) red[r * 256 + tid] = p[r];
    __syncthreads();
    for (int s = 128; s > 0; s >>= 1) {
        if (tid < s)
#pragma unroll
            for (int r = 0; r < 12; r++) red[r * 256 + tid] += red[r * 256 + tid + s];
        __syncthreads();
    }
    if (tid == 0) {
        const float PI4 = 0.7853981633974483f;
        float tr[3], ro[3], scp[3], shp[3];
#pragma unroll
        for (int r = 0; r < 3; r++) {
            tr[r]  = tanhf(red[r * 256] + tb[r]) * 0.1f;
            ro[r]  = tanhf(red[(3 + r) * 256] + rb[r]) * PI4;
            scp[r] = tanhf(red[(6 + r) * 256] + sb_[r]) * 0.2f;
            shp[r] = tanhf(red[(9 + r) * 256] + shb[r]) * PI4;
        }
        float c0 = cosf(ro[0]), s0 = sinf(ro[0]);
        float c1 = cosf(ro[1]), s1 = sinf(ro[1]);
        float c2 = cosf(ro[2]), s2 = sinf(ro[2]);
        float cs0 = cosf(shp[0]), ss0 = sinf(shp[0]);
        float cs1 = cosf(shp[1]), ss1 = sinf(shp[1]);
        float cs2 = cosf(shp[2]), ss2 = sinf(shp[2]);

        float T[16], R1[16], R2[16], R3[16], S[16], H1[16], H2[16], H3[16];
        float R[16], Sh[16], ShT[16], A[16], B[16];
        ident4(T);  T[3] = tr[0]; T[7] = tr[1]; T[11] = tr[2];
        ident4(R1); R1[0] = c0; R1[1] = -s0; R1[4] = s0; R1[5] = c0;
        ident4(R2); R2[5] = c1; R2[6] = -s1; R2[9] = s1; R2[10] = c1;
        ident4(R3); R3[0] = c2; R3[1] = -s2; R3[4] = s2; R3[5] = c2;
        ident4(S);  S[0] = expf(scp[0]); S[5] = expf(scp[1]); S[10] = expf(scp[2]);
        ident4(H1); H1[5] = cs0; H1[6] = -ss0; H1[9] = ss0; H1[10] = cs0;
        ident4(H2); H2[0] = cs1; H2[2] = ss1; H2[8] = -ss1; H2[10] = cs1;
        ident4(H3); H3[0] = cs2; H3[1] = -ss2; H3[4] = ss2; H3[5] = cs2;

        mm4(R1, R2, A); mm4(A, R3, R);
        mm4(H1, H2, A); mm4(A, H3, Sh);
#pragma unroll
        for (int i = 0; i < 4; i++)
#pragma unroll
            for (int j = 0; j < 4; j++) ShT[i * 4 + j] = Sh[j * 4 + i];
        mm4(Sh, S, A); mm4(A, ShT, B); mm4(B, R, A); mm4(A, T, B);
#pragma unroll
        for (int i = 0; i < 12; i++) theta[b * 12 + i] = B[i];
    }
}

// ---------------- trilinear grid sample (zero padding, clamped gather) ----------------
__global__ void __launch_bounds__(256) sampler_kernel(
    const float* __restrict__ x, const float* __restrict__ theta,
    float* __restrict__ out) {
    int idx = blockIdx.x * 256 + threadIdx.x;
    int b = idx >> 18;
    int r = idx & 262143;
    int z = r >> 12, y = (r >> 6) & 63, xq = r & 63;
    const float st = 2.f / 63.f;
    float xx = fmaf((float)xq, st, -1.f);
    float yy = fmaf((float)y, st, -1.f);
    float zz = fmaf((float)z, st, -1.f);
    const float* th = &theta[b * 12];
    float g0 = th[0] * xx + th[1] * yy + th[2] * zz + th[3];
    float g1 = th[4] * xx + th[5] * yy + th[6] * zz + th[7];
    float g2 = th[8] * xx + th[9] * yy + th[10] * zz + th[11];
    float fx = ((g0 + 1.f) * 64.f - 1.f) * 0.5f;
    float fy = ((g1 + 1.f) * 64.f - 1.f) * 0.5f;
    float fz = ((g2 + 1.f) * 64.f - 1.f) * 0.5f;
    float x0f = floorf(fx), y0f = floorf(fy), z0f = floorf(fz);
    int x0 = (int)x0f, y0 = (int)y0f, z0 = (int)z0f;
    float wx1 = fx - x0f, wx0 = 1.f - wx1;
    float wy1 = fy - y0f, wy0 = 1.f - wy1;
    float wz1 = fz - z0f, wz0 = 1.f - wz1;
    const float* xb = &x[b << 18];
    float acc = 0.f;
#pragma unroll
    for (int dz = 0; dz < 2; dz++) {
        int zc = z0 + dz;
        float wz = dz ? wz1 : wz0;
        bool vz = (zc >= 0 && zc < 64);
        int zi = min(max(zc, 0), 63);
#pragma unroll
        for (int dy = 0; dy < 2; dy++) {
            int yc = y0 + dy;
            float wy = dy ? wy1 : wy0;
            bool vy = vz && (yc >= 0 && yc < 64);
            int yi = min(max(yc, 0), 63);
#pragma unroll
            for (int dx = 0; dx < 2; dx++) {
                int xc = x0 + dx;
                float wgt = wz * wy * (dx ? wx1 : wx0);
                bool v = vy && (xc >= 0 && xc < 64);
                int xi = min(max(xc, 0), 63);
                float val = xb[(zi * 64 + yi) * 64 + xi];
                acc += v ? val * wgt : 0.f;
            }
        }
    }
    out[idx] = acc;
}

// ---------------- launch ----------------
extern "C" void kernel_launch(void* const* d_in, const int* in_sizes, int n_in,
                              void* d_out, int out_size) {
    const float* x    = (const float*)d_in[0];
    const float* w00  = (const float*)d_in[1];
    const float* b00  = (const float*)d_in[2];
    const float* g00  = (const float*)d_in[3];
    const float* be00 = (const float*)d_in[4];
    const float* w0   = (const float*)d_in[5];
    const float* b0   = (const float*)d_in[6];
    const float* g0   = (const float*)d_in[7];
    const float* be0  = (const float*)d_in[8];
    const float* w1   = (const float*)d_in[9];
    const float* b1   = (const float*)d_in[10];
    const float* g1   = (const float*)d_in[11];
    const float* be1  = (const float*)d_in[12];
    const float* w2   = (const float*)d_in[13];
    const float* b2   = (const float*)d_in[14];
    const float* g2   = (const float*)d_in[15];
    const float* be2  = (const float*)d_in[16];
    const float* w3   = (const float*)d_in[17];
    const float* b3   = (const float*)d_in[18];
    const float* g3   = (const float*)d_in[19];
    const float* be3  = (const float*)d_in[20];
    const float* tw   = (const float*)d_in[21];
    const float* tb   = (const float*)d_in[22];
    const float* rw   = (const float*)d_in[23];
    const float* rb   = (const float*)d_in[24];
    const float* sw   = (const float*)d_in[25];
    const float* sb   = (const float*)d_in[26];
    const float* shw  = (const float*)d_in[27];
    const float* shb  = (const float*)d_in[28];

    float *buf0, *buf1, *buf2, *buf3, *buf4, *theta;
    float *wT0, *wT1, *wT2;
    double* stats;
    cudaGetSymbolAddress((void**)&buf0, g_buf0);
    cudaGetSymbolAddress((void**)&buf1, g_buf1);
    cudaGetSymbolAddress((void**)&buf2, g_buf2);
    cudaGetSymbolAddress((void**)&buf3, g_buf3);
    cudaGetSymbolAddress((void**)&buf4, g_buf4);
    cudaGetSymbolAddress((void**)&stats, g_stats);
    cudaGetSymbolAddress((void**)&theta, g_theta);
    cudaGetSymbolAddress((void**)&wT0, g_wT0);
    cudaGetSymbolAddress((void**)&wT1, g_wT1);
    cudaGetSymbolAddress((void**)&wT2, g_wT2);

    // v10 smem: input 13*128*4 = 6656 + weights COUTB*27*4
    const int SM_S1 = 13 * 128 * 4 + 32 * 27 * 4;  // 10112
    const int SM_S2 = 13 * 128 * 4 + 64 * 27 * 4;  // 13568
    const int SM_S3 = 13 * 128 * 4 + 32 * 27 * 4;  // 10112
    const int SM_L4 = (16 * 729 + 16 * 16 * 27) * 4;  // 74304 (stage 4)
    cudaFuncSetAttribute(conv_s2_kernel<64, 16, 4>,
                         cudaFuncAttributeMaxDynamicSharedMemorySize, SM_L4);

    // 1: prep (zero stats + all weight transposes)
    prep_kernel<<<702, 256>>>(w0, w1, w2, wT0, wT1, wT2, stats);

    // 2: conv00 1->16, 64^3
    conv00_v2<<<dim3(512, 16), 128>>>(x, w00, b00, buf0, stats + 0);

    // 3: stage 1: 16->32, 64^3 -> 32^3; 256 tiles
    conv_s2_v10<16, 32, 32, 8, 5><<<dim3(256, 16, 1), 128, SM_S1>>>(
        buf0, wT0, b0, stats + 0, g00, be00, 1.f / 4194304.f,
        buf1, stats + 32, 64, 32, 4, 8);

    // 4: stage 2: 32->64, 32^3 -> 16^3; 32 tiles, full 64 oc, OCPT=16 -> 512 blocks
    conv_s2_v10<32, 64, 64, 16, 4><<<dim3(32, 16, 1), 128, SM_S2>>>(
        buf1, wT1, b1, stats + 32, g0, be0, 1.f / 524288.f,
        buf2, stats + 96, 32, 16, 2, 4);

    // 5: stage 3: 64->64, 16^3 -> 8^3; 4 tiles x oc-split z=2 -> 128 blocks
    conv_s2_v10<64, 64, 32, 8, 5><<<dim3(4, 16, 2), 128, SM_S3>>>(
        buf2, wT2, b2, stats + 96, g1, be1, 1.f / 65536.f,
        buf3, stats + 224, 16, 8, 1, 2);

    // 6: stage 4: 64->64, 8^3 -> 4^3 (tiny; old kernel, oc split z=4)
    conv_s2_kernel<64, 16, 4><<<dim3(1, 16, 4), 128, SM_L4>>>(
        buf3, w3, b3, stats + 224, g2, be2, 1.f / 8192.f,
        buf4, stats + 352, 8, 4, 1, 64);

    // 7: heads (inlines stage-4 BN finalize)
    heads_kernel<<<16, 256>>>(buf4, stats + 352, g3, be3, 1.f / 1024.f,
                              tw, tb, rw, rb, sw, sb, shw, shb, theta);

    // 8: grid sample
    sampler_kernel<<<16384, 256>>>(x, theta, (float*)d_out);
}

// round 15
// speedup vs baseline: 1.1898x; 1.0555x over previous
#include <cuda_runtime.h>
#include <math.h>

// ---------------- packed f32x2 helpers (sm_103a FFMA2 path) ----------------
typedef unsigned long long u64t;
__device__ __forceinline__ u64t pack2f(float lo, float hi) {
    u64t r;
    asm("mov.b64 %0, {%1, %2};" : "=l"(r)
        : "r"(__float_as_uint(lo)), "r"(__float_as_uint(hi)));
    return r;
}
__device__ __forceinline__ void ffma2(u64t& d, u64t a, u64t b) {
    asm("fma.rn.f32x2 %0, %1, %2, %0;" : "+l"(d) : "l"(a), "l"(b));
}
__device__ __forceinline__ void unpack2f(u64t v, float& lo, float& hi) {
    unsigned ulo, uhi;
    asm("mov.b64 {%0, %1}, %2;" : "=r"(ulo), "=r"(uhi) : "l"(v));
    lo = __uint_as_float(ulo);
    hi = __uint_as_float(uhi);
}

// ---------------- cp.async helpers ----------------
__device__ __forceinline__ unsigned toShared(const void* p) {
    return (unsigned)__cvta_generic_to_shared(p);
}
__device__ __forceinline__ void cpAsync4(unsigned dst, const float* src) {
    asm volatile("cp.async.ca.shared.global [%0], [%1], 4;" :: "r"(dst), "l"(src));
}
__device__ __forceinline__ void cpAsync16(unsigned dst, const float* src) {
    asm volatile("cp.async.cg.shared.global [%0], [%1], 16;" :: "r"(dst), "l"(src));
}
__device__ __forceinline__ void cpCommit() {
    asm volatile("cp.async.commit_group;");
}
__device__ __forceinline__ void cpWait0() {
    asm volatile("cp.async.wait_group 0;" ::: "memory");
}

// ---------------- persistent device scratch ----------------
__device__ float  g_buf0[16u*16u*64u*64u*64u];
__device__ float  g_buf1[16u*32u*32u*32u*32u];
__device__ float  g_buf2[16u*64u*16u*16u*16u];
__device__ float  g_buf3[16u*64u*8u*8u*8u];
__device__ float  g_buf4[16u*64u*4u*4u*4u];
__device__ double g_stats[480];
__device__ float  g_theta[16*12];
__device__ float  g_wT0[32*16*27];
__device__ float  g_wT1[64*32*27];
__device__ float  g_wT2[64*64*27];

// ---------------- prep: zero stats + all three weight transposes ----------------
__global__ void prep_kernel(const float* __restrict__ w0, const float* __restrict__ w1,
                            const float* __restrict__ w2,
                            float* __restrict__ wT0, float* __restrict__ wT1,
                            float* __restrict__ wT2, double* __restrict__ stats) {
    int i = blockIdx.x * 256 + threadIdx.x;
    if (blockIdx.x == 0) {
        for (int k = threadIdx.x; k < 480; k += 256) stats[k] = 0.0;
    }
    if (i < 13824) {
        int oc = i & 31, icr = i >> 5;
        wT0[i] = w0[oc * 432 + icr];
    } else if (i < 69120) {
        int j = i - 13824;
        int oc = j & 63, icr = j >> 6;
        wT1[j] = w1[oc * 864 + icr];
    } else if (i < 179712) {
        int j = i - 69120;
        int oc = j & 63, icr = j >> 6;
        wT2[j] = w2[oc * 1728 + icr];
    }
}

// ---------------- BN finalize (inline device helper) ----------------
__device__ __forceinline__ void bn_finalize_smem(
    const double* __restrict__ stats_prev, const float* __restrict__ g_prev,
    const float* __restrict__ be_prev, float invN, int C, int tid,
    float* sScale, float* sShift) {
    if (tid < C) {
        double mean = stats_prev[tid] * (double)invN;
        double var  = stats_prev[C + tid] * (double)invN - mean * mean;
        float a = g_prev[tid] * (float)(1.0 / sqrt(var + 1e-5));
        sScale[tid] = a;
        sShift[tid] = be_prev[tid] - (float)mean * a;
    }
}

// ---------------- conv00 v2: 1->16 ch, stride 1, pad 1, 64^3, FFMA2 ----------------
__global__ void __launch_bounds__(128) conv00_v2(
    const float* __restrict__ x, const float* __restrict__ w,
    const float* __restrict__ bias, float* __restrict__ out,
    double* __restrict__ stats) {
    __shared__ float sIn[1000];
    __shared__ float sWd[864];

    int tid = threadIdx.x;
    int b = blockIdx.y;
    int t = blockIdx.x;
    int tz = t >> 6, ty = (t >> 3) & 7, tx = t & 7;

    for (int i = tid; i < 1000; i += 128) {
        int iz = i / 100, iy = (i / 10) % 10, ix = i % 10;
        int gz = tz * 8 - 1 + iz, gy = ty * 8 - 1 + iy, gx = tx * 8 - 1 + ix;
        float v = 0.f;
        if ((unsigned)gz < 64u && (unsigned)gy < 64u && (unsigned)gx < 64u)
            v = x[((b * 64 + gz) * 64 + gy) * 64 + gx];
        sIn[i] = v;
    }
    for (int i = tid; i < 432; i += 128) {
        int k = i >> 4, oc = i & 15;
        float wv = w[oc * 27 + k];
        sWd[k * 32 + oc * 2]     = wv;
        sWd[k * 32 + oc * 2 + 1] = wv;
    }
    __syncthreads();

    int sz = tid >> 4, sy = (tid >> 1) & 7, sx = tid & 1;

    u64t acc[16][2];
#pragma unroll
    for (int oc = 0; oc < 16; oc++) { acc[oc][0] = 0ULL; acc[oc][1] = 0ULL; }

#pragma unroll
    for (int kd = 0; kd < 3; kd++)
#pragma unroll
        for (int kh = 0; kh < 3; kh++) {
            int base = (sz + kd) * 100 + (sy + kh) * 10 + sx * 4;
            float i0 = sIn[base], i1 = sIn[base + 1], i2 = sIn[base + 2];
            float i3 = sIn[base + 3], i4 = sIn[base + 4], i5 = sIn[base + 5];
            u64t P[5];
            P[0] = pack2f(i0, i1); P[1] = pack2f(i1, i2); P[2] = pack2f(i2, i3);
            P[3] = pack2f(i3, i4); P[4] = pack2f(i4, i5);
            int k9 = kd * 3 + kh;
#pragma unroll
            for (int kw = 0; kw < 3; kw++) {
                const u64t* wrow =
                    reinterpret_cast<const u64t*>(&sWd[(k9 * 3 + kw) * 32]);
#pragma unroll
                for (int oc = 0; oc < 16; oc++) {
                    u64t wp = wrow[oc];
                    ffma2(acc[oc][0], P[kw], wp);
                    ffma2(acc[oc][1], P[kw + 2], wp);
                }
            }
        }

    int gz = tz * 8 + sz, gy = ty * 8 + sy, gx = tx * 8 + sx * 4;
#pragma unroll 1
    for (int oc = 0; oc < 16; oc++) {
        float a0, a1, a2, a3;
        unpack2f(acc[oc][0], a0, a1);
        unpack2f(acc[oc][1], a2, a3);
        float bb = bias[oc];
        a0 += bb; a1 += bb; a2 += bb; a3 += bb;
        *reinterpret_cast<float4*>(&out[(((b * 16 + oc) * 64 + gz) * 64 + gy) * 64 + gx]) =
            make_float4(a0, a1, a2, a3);

        float s = a0 + a1 + a2 + a3;
        float q = a0 * a0 + a1 * a1 + a2 * a2 + a3 * a3;
#pragma unroll
        for (int off = 16; off > 0; off >>= 1) {
            s += __shfl_down_sync(0xffffffffu, s, off);
            q += __shfl_down_sync(0xffffffffu, q, off);
        }
        if ((tid & 31) == 0) {
            atomicAdd(&stats[oc], (double)s);
            atomicAdd(&stats[16 + oc], (double)q);
        }
    }
}

// ---------------- conv_s2_v11b: cp.async double-buffered loader (fixed barrier) -----
// FIX vs R14: __syncthreads() after bn_finalize_smem so ALL threads see
// sScale/sShift before the first fixup pass (the R14 failure was this race).
template <int CIN, int COUTT, int COUTB, int OCPT, int MAXB>
__global__ void __launch_bounds__(128, MAXB) conv_s2_v11b(
    const float* __restrict__ in, const float* __restrict__ wT,
    const float* __restrict__ bias,
    const double* __restrict__ statsPrev, const float* __restrict__ gPrev,
    const float* __restrict__ bePrev, float invN,
    float* __restrict__ out, double* __restrict__ stats,
    int Din, int Dout, int ntx, int nty) {
    constexpr int GROUPS = COUTB / OCPT;
    constexpr int THREADS = 32 * GROUPS;
    constexpr int NPAIR = OCPT / 2;
    constexpr int IZ = 9, IYE = 9, IX = 17, IXP = 20;
    constexpr int NINF = IZ * IYE * IXP;                    // 1620
    constexpr int NSLOT = (NINF + THREADS - 1) / THREADS;   // 13
    constexpr int INB = NSLOT * THREADS;
    constexpr int NW = COUTB * 27;
    static_assert(THREADS == 128, "tile mapping assumes 128 threads");
    static_assert((NPAIR & 1) == 0, "NPAIR must be even");

    extern __shared__ float sm[];
    float* sIn = sm;               // 2 * INB floats (double buffer)
    float* sW  = sm + 2 * INB;     // 2 * NW floats (double buffer)
    __shared__ float bsum[COUTB], bsq[COUTB];
    __shared__ float sScale[CIN], sShift[CIN];

    int tid = threadIdx.x;
    int b = blockIdx.y;
    int ocBase = blockIdx.z * COUTB;
    int t = blockIdx.x;
    int tx = t % ntx, ty = (t / ntx) % nty, tz = t / (ntx * nty);

    int vt = tid & 31;
    int group = tid >> 5;
    int oxv = vt & 1;
    int oy  = (vt >> 1) & 3;
    int oz  = vt >> 3;

    bn_finalize_smem(statsPrev, gPrev, bePrev, invN, CIN, tid, sScale, sShift);

    int ginz = tz * 8 - 1;
    int giny = ty * 8 - 1;
    int ginx = tx * 16 - 1;

    const float* inB = in + (long long)b * CIN * Din * Din * Din;
    const int chanStride = Din * Din * Din;

    // per-slot offsets (once per block)
    int goff[NSLOT];
    {
        int i = tid;
#pragma unroll
        for (int s = 0; s < NSLOT; s++, i += THREADS) {
            int ix = i % IXP;
            int r  = i / IXP;
            int iy = r % IYE;
            int iz = r / IYE;
            int gz = ginz + iz, gy = giny + iy, gx = ginx + ix;
            bool ok = (i < NINF) && (ix < IX) &&
                      ((unsigned)gz < (unsigned)Din) &&
                      ((unsigned)gy < (unsigned)Din) &&
                      ((unsigned)gx < (unsigned)Din);
            goff[s] = ok ? ((gz * Din + gy) * Din + gx) : -1;
        }
    }

    unsigned inAddr0 = toShared(&sIn[tid]);
    unsigned wAddr0  = toShared(sW);

    auto issue_in = [&](const float* inC, int buf) {
        unsigned base = inAddr0 + (unsigned)(buf * INB) * 4u;
#pragma unroll
        for (int s = 0; s < NSLOT; s++) {
            int pk = goff[s];
            if (pk >= 0) cpAsync4(base + (unsigned)(s * THREADS) * 4u, inC + pk);
        }
    };
    auto issue_w = [&](int c0, int buf) {
        const float* srcw = wT + c0 * 27 * COUTT;
        unsigned base = wAddr0 + (unsigned)(buf * NW) * 4u;
        if (COUTB == COUTT) {
#pragma unroll
            for (int i = tid * 4; i < NW; i += THREADS * 4)
                cpAsync16(base + (unsigned)i * 4u, &srcw[i]);
        } else {
#pragma unroll
            for (int i = tid * 4; i < NW; i += THREADS * 4) {
                int ocl = i % COUTB;
                int row = i / COUTB;
                cpAsync16(base + (unsigned)i * 4u, &srcw[row * COUTT + ocBase + ocl]);
            }
        }
    };

    u64t acc[NPAIR][4];
#pragma unroll
    for (int p = 0; p < NPAIR; p++)
#pragma unroll
        for (int u = 0; u < 4; u++) acc[p][u] = 0ULL;

    // prologue: start channel 0 + weights 0
    issue_in(inB, 0);
    issue_w(0, 0);
    cpCommit();

    __syncthreads();   // FIX: sScale/sShift visible to ALL threads before first fixup

#pragma unroll 1
    for (int c0 = 0; c0 < CIN; c0++) {
        int cur = c0 & 1;
        cpWait0();                 // buf[cur] data arrived (own slots)
        float sc = sScale[c0], sh = sShift[c0];
        float* bufp = &sIn[cur * INB];
#pragma unroll
        for (int s = 0; s < NSLOT; s++) {
            int idx = s * THREADS + tid;
            float v = 0.f;
            if (goff[s] >= 0) v = fmaxf(fmaf(bufp[idx], sc, sh), 0.f);
            bufp[idx] = v;
        }
        __syncthreads();           // all fixed + all done computing buf[cur^1]

        if (c0 + 1 < CIN) {
            issue_in(inB + (c0 + 1) * chanStride, cur ^ 1);
            issue_w(c0 + 1, cur ^ 1);
            cpCommit();
        }

        const float* wCur = &sW[cur * NW];
#pragma unroll
        for (int kd = 0; kd < 3; kd++)
#pragma unroll
            for (int kh = 0; kh < 3; kh++) {
                const float* ip =
                    &bufp[((2 * oz + kd) * IYE + (2 * oy + kh)) * IXP + 8 * oxv];
                float4 va = *reinterpret_cast<const float4*>(ip);
                float4 vb = *reinterpret_cast<const float4*>(ip + 4);
                float v8 = ip[8];
                u64t ivd[9];
                ivd[0] = pack2f(va.x, va.x); ivd[1] = pack2f(va.y, va.y);
                ivd[2] = pack2f(va.z, va.z); ivd[3] = pack2f(va.w, va.w);
                ivd[4] = pack2f(vb.x, vb.x); ivd[5] = pack2f(vb.y, vb.y);
                ivd[6] = pack2f(vb.z, vb.z); ivd[7] = pack2f(vb.w, vb.w);
                ivd[8] = pack2f(v8, v8);
                int k9 = kd * 3 + kh;
                const float* wb_ = &wCur[(k9 * 3) * COUTB + group * OCPT];
#pragma unroll
                for (int kw = 0; kw < 3; kw++) {
                    ulonglong2 wq[NPAIR / 2];
#pragma unroll
                    for (int pp = 0; pp < NPAIR / 2; pp++)
                        wq[pp] = *reinterpret_cast<const ulonglong2*>(
                            wb_ + kw * COUTB + pp * 4);
#pragma unroll
                    for (int u = 0; u < 4; u++) {
                        u64t iv = ivd[2 * u + kw];
#pragma unroll
                        for (int pp = 0; pp < NPAIR / 2; pp++) {
                            ffma2(acc[2 * pp][u], wq[pp].x, iv);
                            ffma2(acc[2 * pp + 1][u], wq[pp].y, iv);
                        }
                    }
                }
            }
    }

    int gz = tz * 4 + oz, gy = ty * 4 + oy;
    int gx = tx * 8 + oxv * 4;
#pragma unroll 1
    for (int p = 0; p < NPAIR; p++) {
        float o0[4], o1[4];
#pragma unroll
        for (int u = 0; u < 4; u++) unpack2f(acc[p][u], o0[u], o1[u]);
#pragma unroll
        for (int h = 0; h < 2; h++) {
            float* ov = h ? o1 : o0;
            int ocl = group * OCPT + 2 * p + h;
            int oc = ocBase + ocl;
            float bb = bias[oc];
            float a0 = ov[0] + bb, a1 = ov[1] + bb, a2 = ov[2] + bb, a3 = ov[3] + bb;
            *reinterpret_cast<float4*>(
                &out[(((b * COUTT + oc) * Dout + gz) * Dout + gy) * Dout + gx]) =
                make_float4(a0, a1, a2, a3);

            float s = a0 + a1 + a2 + a3;
            float q = a0 * a0 + a1 * a1 + a2 * a2 + a3 * a3;
#pragma unroll
            for (int off = 16; off > 0; off >>= 1) {
                s += __shfl_down_sync(0xffffffffu, s, off);
                q += __shfl_down_sync(0xffffffffu, q, off);
            }
            if (vt == 0) { bsum[ocl] = s; bsq[ocl] = q; }
        }
    }
    __syncthreads();
    if (tid < COUTB) {
        atomicAdd(&stats[ocBase + tid], (double)bsum[tid]);
        atomicAdd(&stats[COUTT + ocBase + tid], (double)bsq[tid]);
    }
}

// ---------------- old generic stride-2 conv (stage 4) + inline finalize ------------
template <int CIN, int COUTB, int OCPT>
__global__ void __launch_bounds__(128) conv_s2_kernel(
    const float* __restrict__ in, const float* __restrict__ w,
    const float* __restrict__ bias,
    const double* __restrict__ statsPrev, const float* __restrict__ gPrev,
    const float* __restrict__ bePrev, float invN,
    float* __restrict__ out, double* __restrict__ stats,
    int Din, int Dout, int ntile, int coutTot) {
    constexpr int ICC = 16;
    constexpr int NIN = ICC * 729;
    constexpr int NW  = COUTB * ICC * 27;
    extern __shared__ float sm[];
    float* sIn = sm;
    float* sW  = sm + NIN;
    __shared__ float bsum[COUTB], bsq[COUTB];
    __shared__ float sScale[CIN], sShift[CIN];

    int tid = threadIdx.x;
    int b = blockIdx.y;
    int ocBase = blockIdx.z * COUTB;
    int t = blockIdx.x;
    int tz = t / (ntile * ntile), ty = (t / ntile) % ntile, tx = t % ntile;
    int pair = tid & 31, group = tid >> 5;
    int oz = pair >> 3, oy = (pair >> 1) & 3, px = pair & 1;

    bn_finalize_smem(statsPrev, gPrev, bePrev, invN, CIN, tid, sScale, sShift);

    if (tid < COUTB) { bsum[tid] = 0.f; bsq[tid] = 0.f; }

    float acc0[OCPT], acc1[OCPT];
#pragma unroll
    for (int j = 0; j < OCPT; j++) { acc0[j] = 0.f; acc1[j] = 0.f; }

    for (int c0 = 0; c0 < CIN; c0 += ICC) {
        __syncthreads();
        for (int i = tid; i < NIN; i += 128) {
            int ic = i / 729, r = i % 729;
            int iz = r / 81, iy = (r / 9) % 9, ix = r % 9;
            int gz = tz * 8 - 1 + iz, gy = ty * 8 - 1 + iy, gx = tx * 8 - 1 + ix;
            float v = 0.f;
            if ((unsigned)gz < (unsigned)Din && (unsigned)gy < (unsigned)Din &&
                (unsigned)gx < (unsigned)Din) {
                v = in[(((b * CIN + c0 + ic) * Din + gz) * Din + gy) * Din + gx];
                v = fmaxf(fmaf(v, sScale[c0 + ic], sShift[c0 + ic]), 0.f);
            }
            sIn[i] = v;
        }
        for (int i = tid; i < NW; i += 128) {
            int ocl = i / (ICC * 27), r = i % (ICC * 27);
            sW[i] = w[((ocBase + ocl) * CIN + c0) * 27 + r];
        }
        __syncthreads();

#pragma unroll 1
        for (int ic = 0; ic < ICC; ic++) {
            const float* wrow = &sW[(group * OCPT) * ICC * 27 + ic * 27];
#pragma unroll
            for (int kd = 0; kd < 3; kd++)
#pragma unroll
                for (int kh = 0; kh < 3; kh++) {
                    int base = ((ic * 9 + (2 * oz + kd)) * 9 + (2 * oy + kh)) * 9 + 4 * px;
                    float ivs[5];
#pragma unroll
                    for (int u = 0; u < 5; u++) ivs[u] = sIn[base + u];
#pragma unroll
                    for (int kw = 0; kw < 3; kw++) {
#pragma unroll
                        for (int j = 0; j < OCPT; j++) {
                            float wv = wrow[j * ICC * 27 + (kd * 3 + kh) * 3 + kw];
                            acc0[j] = fmaf(ivs[kw], wv, acc0[j]);
                            acc1[j] = fmaf(ivs[kw + 2], wv, acc1[j]);
                        }
                    }
                }
        }
    }

    int gz = tz * 4 + oz, gy = ty * 4 + oy, gx = tx * 4 + 2 * px;
#pragma unroll
    for (int j = 0; j < OCPT; j++) {
        int oc = ocBase + group * OCPT + j;
        float bb = bias[oc];
        float o0 = acc0[j] + bb, o1 = acc1[j] + bb;
        *reinterpret_cast<float2*>(
            &out[(((b * coutTot + oc) * Dout + gz) * Dout + gy) * Dout + gx]) =
            make_float2(o0, o1);

        float s = o0 + o1, q = o0 * o0 + o1 * o1;
#pragma unroll
        for (int off = 16; off > 0; off >>= 1) {
            s += __shfl_down_sync(0xffffffffu, s, off);
            q += __shfl_down_sync(0xffffffffu, q, off);
        }
        if (pair == 0) {
            atomicAdd(&bsum[group * OCPT + j], s);
            atomicAdd(&bsq[group * OCPT + j], q);
        }
    }
    __syncthreads();
    if (tid < COUTB) {
        atomicAdd(&stats[ocBase + tid], (double)bsum[tid]);
        atomicAdd(&stats[coutTot + ocBase + tid], (double)bsq[tid]);
    }
}

// ---------------- heads: BN finalize + 12 dot products + matrix composition --------
__device__ __forceinline__ void ident4(float* M) {
#pragma unroll
    for (int i = 0; i < 16; i++) M[i] = (i % 5 == 0) ? 1.f : 0.f;
}
__device__ __forceinline__ void mm4(const float* A, const float* B, float* C) {
#pragma unroll
    for (int i = 0; i < 4; i++)
#pragma unroll
        for (int j = 0; j < 4; j++)
            C[i * 4 + j] = A[i * 4 + 0] * B[0 + j] + A[i * 4 + 1] * B[4 + j] +
                           A[i * 4 + 2] * B[8 + j] + A[i * 4 + 3] * B[12 + j];
}

__global__ void __launch_bounds__(256) heads_kernel(
    const float* __restrict__ xs,
    const double* __restrict__ statsPrev, const float* __restrict__ gPrev,
    const float* __restrict__ bePrev, float invN,
    const float* __restrict__ tw, const float* __restrict__ tb,
    const float* __restrict__ rw, const float* __restrict__ rb,
    const float* __restrict__ sw_, const float* __restrict__ sb_,
    const float* __restrict__ shw, const float* __restrict__ shb,
    float* __restrict__ theta) {
    __shared__ float red[12 * 256];
    __shared__ float ssc[64], ssh[64];
    int b = blockIdx.x, tid = threadIdx.x;
    bn_finalize_smem(statsPrev, gPrev, bePrev, invN, 64, tid, ssc, ssh);
    __syncthreads();
    float p[12];
#pragma unroll
    for (int r = 0; r < 12; r++) p[r] = 0.f;
    for (int i = tid; i < 4096; i += 256) {
        int c = i >> 6;
        float v = fmaxf(fmaf(xs[b * 4096 + i], ssc[c], ssh[c]), 0.f);
#pragma unroll
        for (int r = 0; r < 3; r++) {
            p[r]     = fmaf(v, tw[r * 4096 + i], p[r]);
            p[3 + r] = fmaf(v, rw[r * 4096 + i], p[3 + r]);
            p[6 + r] = fmaf(v, sw_[r * 4096 + i], p[6 + r]);
            p[9 + r] = fmaf(v, shw[r * 4096 + i], p[9 + r]);
        }
    }
#pragma unroll
    for (int r = 0; r < 12; r++) red[r * 256 + tid] = p[r];
    __syncthreads();
    for (int s = 128; s > 0; s >>= 1) {
        if (tid < s)
#pragma unroll
            for (int r = 0; r < 12; r++) red[r * 256 + tid] += red[r * 256 + tid + s];
        __syncthreads();
    }
    if (tid == 0) {
        const float PI4 = 0.7853981633974483f;
        float tr[3], ro[3], scp[3], shp[3];
#pragma unroll
        for (int r = 0; r < 3; r++) {
            tr[r]  = tanhf(red[r * 256] + tb[r]) * 0.1f;
            ro[r]  = tanhf(red[(3 + r) * 256] + rb[r]) * PI4;
            scp[r] = tanhf(red[(6 + r) * 256] + sb_[r]) * 0.2f;
            shp[r] = tanhf(red[(9 + r) * 256] + shb[r]) * PI4;
        }
        float c0 = cosf(ro[0]), s0 = sinf(ro[0]);
        float c1 = cosf(ro[1]), s1 = sinf(ro[1]);
        float c2 = cosf(ro[2]), s2 = sinf(ro[2]);
        float cs0 = cosf(shp[0]), ss0 = sinf(shp[0]);
        float cs1 = cosf(shp[1]), ss1 = sinf(shp[1]);
        float cs2 = cosf(shp[2]), ss2 = sinf(shp[2]);

        float T[16], R1[16], R2[16], R3[16], S[16], H1[16], H2[16], H3[16];
        float R[16], Sh[16], ShT[16], A[16], B[16];
        ident4(T);  T[3] = tr[0]; T[7] = tr[1]; T[11] = tr[2];
        ident4(R1); R1[0] = c0; R1[1] = -s0; R1[4] = s0; R1[5] = c0;
        ident4(R2); R2[5] = c1; R2[6] = -s1; R2[9] = s1; R2[10] = c1;
        ident4(R3); R3[0] = c2; R3[1] = -s2; R3[4] = s2; R3[5] = c2;
        ident4(S);  S[0] = expf(scp[0]); S[5] = expf(scp[1]); S[10] = expf(scp[2]);
        ident4(H1); H1[5] = cs0; H1[6] = -ss0; H1[9] = ss0; H1[10] = cs0;
        ident4(H2); H2[0] = cs1; H2[2] = ss1; H2[8] = -ss1; H2[10] = cs1;
        ident4(H3); H3[0] = cs2; H3[1] = -ss2; H3[4] = ss2; H3[5] = cs2;

        mm4(R1, R2, A); mm4(A, R3, R);
        mm4(H1, H2, A); mm4(A, H3, Sh);
#pragma unroll
        for (int i = 0; i < 4; i++)
#pragma unroll
            for (int j = 0; j < 4; j++) ShT[i * 4 + j] = Sh[j * 4 + i];
        mm4(Sh, S, A); mm4(A, ShT, B); mm4(B, R, A); mm4(A, T, B);
#pragma unroll
        for (int i = 0; i < 12; i++) theta[b * 12 + i] = B[i];
    }
}

// ---------------- trilinear grid sample (zero padding, clamped gather) ----------------
__global__ void __launch_bounds__(256) sampler_kernel(
    const float* __restrict__ x, const float* __restrict__ theta,
    float* __restrict__ out) {
    int idx = blockIdx.x * 256 + threadIdx.x;
    int b = idx >> 18;
    int r = idx & 262143;
    int z = r >> 12, y = (r >> 6) & 63, xq = r & 63;
    const float st = 2.f / 63.f;
    float xx = fmaf((float)xq, st, -1.f);
    float yy = fmaf((float)y, st, -1.f);
    float zz = fmaf((float)z, st, -1.f);
    const float* th = &theta[b * 12];
    float g0 = th[0] * xx + th[1] * yy + th[2] * zz + th[3];
    float g1 = th[4] * xx + th[5] * yy + th[6] * zz + th[7];
    float g2 = th[8] * xx + th[9] * yy + th[10] * zz + th[11];
    float fx = ((g0 + 1.f) * 64.f - 1.f) * 0.5f;
    float fy = ((g1 + 1.f) * 64.f - 1.f) * 0.5f;
    float fz = ((g2 + 1.f) * 64.f - 1.f) * 0.5f;
    float x0f = floorf(fx), y0f = floorf(fy), z0f = floorf(fz);
    int x0 = (int)x0f, y0 = (int)y0f, z0 = (int)z0f;
    float wx1 = fx - x0f, wx0 = 1.f - wx1;
    float wy1 = fy - y0f, wy0 = 1.f - wy1;
    float wz1 = fz - z0f, wz0 = 1.f - wz1;
    const float* xb = &x[b << 18];
    float acc = 0.f;
#pragma unroll
    for (int dz = 0; dz < 2; dz++) {
        int zc = z0 + dz;
        float wz = dz ? wz1 : wz0;
        bool vz = (zc >= 0 && zc < 64);
        int zi = min(max(zc, 0), 63);
#pragma unroll
        for (int dy = 0; dy < 2; dy++) {
            int yc = y0 + dy;
            float wy = dy ? wy1 : wy0;
            bool vy = vz && (yc >= 0 && yc < 64);
            int yi = min(max(yc, 0), 63);
#pragma unroll
            for (int dx = 0; dx < 2; dx++) {
                int xc = x0 + dx;
                float wgt = wz * wy * (dx ? wx1 : wx0);
                bool v = vy && (xc >= 0 && xc < 64);
                int xi = min(max(xc, 0), 63);
                float val = xb[(zi * 64 + yi) * 64 + xi];
                acc += v ? val * wgt : 0.f;
            }
        }
    }
    out[idx] = acc;
}

// ---------------- launch ----------------
extern "C" void kernel_launch(void* const* d_in, const int* in_sizes, int n_in,
                              void* d_out, int out_size) {
    const float* x    = (const float*)d_in[0];
    const float* w00  = (const float*)d_in[1];
    const float* b00  = (const float*)d_in[2];
    const float* g00  = (const float*)d_in[3];
    const float* be00 = (const float*)d_in[4];
    const float* w0   = (const float*)d_in[5];
    const float* b0   = (const float*)d_in[6];
    const float* g0   = (const float*)d_in[7];
    const float* be0  = (const float*)d_in[8];
    const float* w1   = (const float*)d_in[9];
    const float* b1   = (const float*)d_in[10];
    const float* g1   = (const float*)d_in[11];
    const float* be1  = (const float*)d_in[12];
    const float* w2   = (const float*)d_in[13];
    const float* b2   = (const float*)d_in[14];
    const float* g2   = (const float*)d_in[15];
    const float* be2  = (const float*)d_in[16];
    const float* w3   = (const float*)d_in[17];
    const float* b3   = (const float*)d_in[18];
    const float* g3   = (const float*)d_in[19];
    const float* be3  = (const float*)d_in[20];
    const float* tw   = (const float*)d_in[21];
    const float* tb   = (const float*)d_in[22];
    const float* rw   = (const float*)d_in[23];
    const float* rb   = (const float*)d_in[24];
    const float* sw   = (const float*)d_in[25];
    const float* sb   = (const float*)d_in[26];
    const float* shw  = (const float*)d_in[27];
    const float* shb  = (const float*)d_in[28];

    float *buf0, *buf1, *buf2, *buf3, *buf4, *theta;
    float *wT0, *wT1, *wT2;
    double* stats;
    cudaGetSymbolAddress((void**)&buf0, g_buf0);
    cudaGetSymbolAddress((void**)&buf1, g_buf1);
    cudaGetSymbolAddress((void**)&buf2, g_buf2);
    cudaGetSymbolAddress((void**)&buf3, g_buf3);
    cudaGetSymbolAddress((void**)&buf4, g_buf4);
    cudaGetSymbolAddress((void**)&stats, g_stats);
    cudaGetSymbolAddress((void**)&theta, g_theta);
    cudaGetSymbolAddress((void**)&wT0, g_wT0);
    cudaGetSymbolAddress((void**)&wT1, g_wT1);
    cudaGetSymbolAddress((void**)&wT2, g_wT2);

    // v11 smem: input 2*13*128*4 = 13312 + weights 2*COUTB*27*4
    const int SM_S1 = 2 * 13 * 128 * 4 + 2 * 32 * 27 * 4;  // 20224
    const int SM_S2 = 2 * 13 * 128 * 4 + 2 * 64 * 27 * 4;  // 27136
    const int SM_S3 = 2 * 13 * 128 * 4 + 2 * 32 * 27 * 4;  // 20224
    const int SM_L4 = (16 * 729 + 16 * 16 * 27) * 4;       // 74304 (stage 4)
    cudaFuncSetAttribute(conv_s2_kernel<64, 16, 4>,
                         cudaFuncAttributeMaxDynamicSharedMemorySize, SM_L4);

    // 1: prep (zero stats + all weight transposes)
    prep_kernel<<<702, 256>>>(w0, w1, w2, wT0, wT1, wT2, stats);

    // 2: conv00 1->16, 64^3
    conv00_v2<<<dim3(512, 16), 128>>>(x, w00, b00, buf0, stats + 0);

    // 3: stage 1: 16->32, 64^3 -> 32^3; 256 tiles
    conv_s2_v11b<16, 32, 32, 8, 5><<<dim3(256, 16, 1), 128, SM_S1>>>(
        buf0, wT0, b0, stats + 0, g00, be00, 1.f / 4194304.f,
        buf1, stats + 32, 64, 32, 4, 8);

    // 4: stage 2: 32->64, 32^3 -> 16^3; 32 tiles, full 64 oc, OCPT=16 -> 512 blocks
    conv_s2_v11b<32, 64, 64, 16, 4><<<dim3(32, 16, 1), 128, SM_S2>>>(
        buf1, wT1, b1, stats + 32, g0, be0, 1.f / 524288.f,
        buf2, stats + 96, 32, 16, 2, 4);

    // 5: stage 3: 64->64, 16^3 -> 8^3; 4 tiles x oc-split z=2 -> 128 blocks
    conv_s2_v11b<64, 64, 32, 8, 5><<<dim3(4, 16, 2), 128, SM_S3>>>(
        buf2, wT2, b2, stats + 96, g1, be1, 1.f / 65536.f,
        buf3, stats + 224, 16, 8, 1, 2);

    // 6: stage 4: 64->64, 8^3 -> 4^3 (tiny; old kernel, oc split z=4)
    conv_s2_kernel<64, 16, 4><<<dim3(1, 16, 4), 128, SM_L4>>>(
        buf3, w3, b3, stats + 224, g2, be2, 1.f / 8192.f,
        buf4, stats + 352, 8, 4, 1, 64);

    // 7: heads (inlines stage-4 BN finalize)
    heads_kernel<<<16, 256>>>(buf4, stats + 352, g3, be3, 1.f / 1024.f,
                              tw, tb, rw, rb, sw, sb, shw, shb, theta);

    // 8: grid sample
    sampler_kernel<<<16384, 256>>>(x, theta, (float*)d_out);
}

// round 16
// speedup vs baseline: 1.2231x; 1.0280x over previous
#include <cuda_runtime.h>
#include <math.h>

// ---------------- packed f32x2 helpers (sm_103a FFMA2 path) ----------------
typedef unsigned long long u64t;
__device__ __forceinline__ u64t pack2f(float lo, float hi) {
    u64t r;
    asm("mov.b64 %0, {%1, %2};" : "=l"(r)
        : "r"(__float_as_uint(lo)), "r"(__float_as_uint(hi)));
    return r;
}
__device__ __forceinline__ void ffma2(u64t& d, u64t a, u64t b) {
    asm("fma.rn.f32x2 %0, %1, %2, %0;" : "+l"(d) : "l"(a), "l"(b));
}
__device__ __forceinline__ void unpack2f(u64t v, float& lo, float& hi) {
    unsigned ulo, uhi;
    asm("mov.b64 {%0, %1}, %2;" : "=r"(ulo), "=r"(uhi) : "l"(v));
    lo = __uint_as_float(ulo);
    hi = __uint_as_float(uhi);
}

// ---------------- cp.async helpers ----------------
__device__ __forceinline__ unsigned toShared(const void* p) {
    return (unsigned)__cvta_generic_to_shared(p);
}
__device__ __forceinline__ void cpAsync4(unsigned dst, const float* src) {
    asm volatile("cp.async.ca.shared.global [%0], [%1], 4;" :: "r"(dst), "l"(src));
}
__device__ __forceinline__ void cpAsync16(unsigned dst, const float* src) {
    asm volatile("cp.async.cg.shared.global [%0], [%1], 16;" :: "r"(dst), "l"(src));
}
__device__ __forceinline__ void cpCommit() {
    asm volatile("cp.async.commit_group;");
}
__device__ __forceinline__ void cpWait0() {
    asm volatile("cp.async.wait_group 0;" ::: "memory");
}

// ---------------- persistent device scratch ----------------
__device__ float  g_buf0[16u*16u*64u*64u*64u];
__device__ float  g_buf1[16u*32u*32u*32u*32u];
__device__ float  g_buf2[16u*64u*16u*16u*16u];
__device__ float  g_buf3[16u*64u*8u*8u*8u];
__device__ float  g_buf4[16u*64u*4u*4u*4u];
__device__ double g_stats[480];
__device__ float  g_theta[16*12];
__device__ float  g_wT0[32*16*27];
__device__ float  g_wT1[64*32*27];
__device__ float  g_wT2[64*64*27];

// ---------------- prep: zero stats + all three weight transposes ----------------
__global__ void prep_kernel(const float* __restrict__ w0, const float* __restrict__ w1,
                            const float* __restrict__ w2,
                            float* __restrict__ wT0, float* __restrict__ wT1,
                            float* __restrict__ wT2, double* __restrict__ stats) {
    int i = blockIdx.x * 256 + threadIdx.x;
    if (blockIdx.x == 0) {
        for (int k = threadIdx.x; k < 480; k += 256) stats[k] = 0.0;
    }
    if (i < 13824) {
        int oc = i & 31, icr = i >> 5;
        wT0[i] = w0[oc * 432 + icr];
    } else if (i < 69120) {
        int j = i - 13824;
        int oc = j & 63, icr = j >> 6;
        wT1[j] = w1[oc * 864 + icr];
    } else if (i < 179712) {
        int j = i - 69120;
        int oc = j & 63, icr = j >> 6;
        wT2[j] = w2[oc * 1728 + icr];
    }
}

// ---------------- BN finalize (inline device helper) ----------------
__device__ __forceinline__ void bn_finalize_smem(
    const double* __restrict__ stats_prev, const float* __restrict__ g_prev,
    const float* __restrict__ be_prev, float invN, int C, int tid,
    float* sScale, float* sShift) {
    if (tid < C) {
        double mean = stats_prev[tid] * (double)invN;
        double var  = stats_prev[C + tid] * (double)invN - mean * mean;
        float a = g_prev[tid] * (float)(1.0 / sqrt(var + 1e-5));
        sScale[tid] = a;
        sShift[tid] = be_prev[tid] - (float)mean * a;
    }
}

// ---------------- conv00 v2: 1->16 ch, stride 1, pad 1, 64^3, FFMA2 ----------------
__global__ void __launch_bounds__(128) conv00_v2(
    const float* __restrict__ x, const float* __restrict__ w,
    const float* __restrict__ bias, float* __restrict__ out,
    double* __restrict__ stats) {
    __shared__ float sIn[1000];
    __shared__ float sWd[864];

    int tid = threadIdx.x;
    int b = blockIdx.y;
    int t = blockIdx.x;
    int tz = t >> 6, ty = (t >> 3) & 7, tx = t & 7;

    for (int i = tid; i < 1000; i += 128) {
        int iz = i / 100, iy = (i / 10) % 10, ix = i % 10;
        int gz = tz * 8 - 1 + iz, gy = ty * 8 - 1 + iy, gx = tx * 8 - 1 + ix;
        float v = 0.f;
        if ((unsigned)gz < 64u && (unsigned)gy < 64u && (unsigned)gx < 64u)
            v = x[((b * 64 + gz) * 64 + gy) * 64 + gx];
        sIn[i] = v;
    }
    for (int i = tid; i < 432; i += 128) {
        int k = i >> 4, oc = i & 15;
        float wv = w[oc * 27 + k];
        sWd[k * 32 + oc * 2]     = wv;
        sWd[k * 32 + oc * 2 + 1] = wv;
    }
    __syncthreads();

    int sz = tid >> 4, sy = (tid >> 1) & 7, sx = tid & 1;

    u64t acc[16][2];
#pragma unroll
    for (int oc = 0; oc < 16; oc++) { acc[oc][0] = 0ULL; acc[oc][1] = 0ULL; }

#pragma unroll
    for (int kd = 0; kd < 3; kd++)
#pragma unroll
        for (int kh = 0; kh < 3; kh++) {
            int base = (sz + kd) * 100 + (sy + kh) * 10 + sx * 4;
            float i0 = sIn[base], i1 = sIn[base + 1], i2 = sIn[base + 2];
            float i3 = sIn[base + 3], i4 = sIn[base + 4], i5 = sIn[base + 5];
            u64t P[5];
            P[0] = pack2f(i0, i1); P[1] = pack2f(i1, i2); P[2] = pack2f(i2, i3);
            P[3] = pack2f(i3, i4); P[4] = pack2f(i4, i5);
            int k9 = kd * 3 + kh;
#pragma unroll
            for (int kw = 0; kw < 3; kw++) {
                const u64t* wrow =
                    reinterpret_cast<const u64t*>(&sWd[(k9 * 3 + kw) * 32]);
#pragma unroll
                for (int oc = 0; oc < 16; oc++) {
                    u64t wp = wrow[oc];
                    ffma2(acc[oc][0], P[kw], wp);
                    ffma2(acc[oc][1], P[kw + 2], wp);
                }
            }
        }

    int gz = tz * 8 + sz, gy = ty * 8 + sy, gx = tx * 8 + sx * 4;
#pragma unroll 1
    for (int oc = 0; oc < 16; oc++) {
        float a0, a1, a2, a3;
        unpack2f(acc[oc][0], a0, a1);
        unpack2f(acc[oc][1], a2, a3);
        float bb = bias[oc];
        a0 += bb; a1 += bb; a2 += bb; a3 += bb;
        *reinterpret_cast<float4*>(&out[(((b * 16 + oc) * 64 + gz) * 64 + gy) * 64 + gx]) =
            make_float4(a0, a1, a2, a3);

        float s = a0 + a1 + a2 + a3;
        float q = a0 * a0 + a1 * a1 + a2 * a2 + a3 * a3;
#pragma unroll
        for (int off = 16; off > 0; off >>= 1) {
            s += __shfl_down_sync(0xffffffffu, s, off);
            q += __shfl_down_sync(0xffffffffu, q, off);
        }
        if ((tid & 31) == 0) {
            atomicAdd(&stats[oc], (double)s);
            atomicAdd(&stats[16 + oc], (double)q);
        }
    }
}

// ---------------- conv_s2_v12: stage-1 (COUTB=32, OCPT=8) with VPT=8 ---------------
// Tile 4x4x16 outputs. Each lane: 8 x-outputs in two 4-wide halves (ivd reused).
// Per (ic,k9): 6 hoisted weight LDS, then 2x(2 LDS.128+LDS.32+9 packs+48 FFMA2)
// -> 96 FFMA2 per k9 (stage-2 density). cp.async double-buffered pipeline.
template <int CIN, int MAXB>
__global__ void __launch_bounds__(128, MAXB) conv_s2_v12(
    const float* __restrict__ in, const float* __restrict__ wT,
    const float* __restrict__ bias,
    const double* __restrict__ statsPrev, const float* __restrict__ gPrev,
    const float* __restrict__ bePrev, float invN,
    float* __restrict__ out, double* __restrict__ stats,
    int Din, int Dout, int ntx, int nty) {
    constexpr int COUTB = 32, OCPT = 8;
    constexpr int THREADS = 128;
    constexpr int NPAIR = OCPT / 2;     // 4
    constexpr int IZ = 9, IYE = 9, IX = 33, IXP = 36;  // x-tile 16 outputs
    constexpr int NINF = IZ * IYE * IXP;               // 2916
    constexpr int NSLOT = (NINF + THREADS - 1) / THREADS;  // 23
    constexpr int INB = NSLOT * THREADS;               // 2944
    constexpr int NW = COUTB * 27;                     // 864

    extern __shared__ float sm[];
    float* sIn = sm;               // 2 * INB
    float* sW  = sm + 2 * INB;     // 2 * NW
    __shared__ float bsum[COUTB], bsq[COUTB];
    __shared__ float sScale[CIN], sShift[CIN];

    int tid = threadIdx.x;
    int b = blockIdx.y;
    int t = blockIdx.x;
    int tx = t % ntx, ty = (t / ntx) % nty, tz = t / (ntx * nty);

    int vt = tid & 31;
    int group = tid >> 5;          // 4 oc-groups
    int oxv = vt & 1;              // 2 x-lanes (8 outputs each)
    int oy  = (vt >> 1) & 3;
    int oz  = vt >> 3;

    bn_finalize_smem(statsPrev, gPrev, bePrev, invN, CIN, tid, sScale, sShift);

    int ginz = tz * 8 - 1;
    int giny = ty * 8 - 1;
    int ginx = tx * 32 - 1;

    const float* inB = in + (long long)b * CIN * Din * Din * Din;
    const int chanStride = Din * Din * Din;

    int goff[NSLOT];
    {
        int i = tid;
#pragma unroll
        for (int s = 0; s < NSLOT; s++, i += THREADS) {
            int ix = i % IXP;
            int r  = i / IXP;
            int iy = r % IYE;
            int iz = r / IYE;
            int gz = ginz + iz, gy = giny + iy, gx = ginx + ix;
            bool ok = (i < NINF) && (ix < IX) &&
                      ((unsigned)gz < (unsigned)Din) &&
                      ((unsigned)gy < (unsigned)Din) &&
                      ((unsigned)gx < (unsigned)Din);
            goff[s] = ok ? ((gz * Din + gy) * Din + gx) : -1;
        }
    }

    unsigned inAddr0 = toShared(&sIn[tid]);
    unsigned wAddr0  = toShared(sW);

    auto issue_in = [&](const float* inC, int buf) {
        unsigned base = inAddr0 + (unsigned)(buf * INB) * 4u;
#pragma unroll
        for (int s = 0; s < NSLOT; s++) {
            int pk = goff[s];
            if (pk >= 0) cpAsync4(base + (unsigned)(s * THREADS) * 4u, inC + pk);
        }
    };
    auto issue_w = [&](int c0, int buf) {
        const float* srcw = wT + c0 * 27 * COUTB;
        unsigned base = wAddr0 + (unsigned)(buf * NW) * 4u;
#pragma unroll
        for (int i = tid * 4; i < NW; i += THREADS * 4)
            cpAsync16(base + (unsigned)i * 4u, &srcw[i]);
    };

    u64t acc[NPAIR][2][4];   // [oc-pair][x-half][x-sub]
#pragma unroll
    for (int p = 0; p < NPAIR; p++)
#pragma unroll
        for (int h = 0; h < 2; h++)
#pragma unroll
            for (int u = 0; u < 4; u++) acc[p][h][u] = 0ULL;

    issue_in(inB, 0);
    issue_w(0, 0);
    cpCommit();

    __syncthreads();   // sScale/sShift visible to all threads

#pragma unroll 1
    for (int c0 = 0; c0 < CIN; c0++) {
        int cur = c0 & 1;
        cpWait0();
        float sc = sScale[c0], sh = sShift[c0];
        float* bufp = &sIn[cur * INB];
#pragma unroll
        for (int s = 0; s < NSLOT; s++) {
            int idx = s * THREADS + tid;
            float v = 0.f;
            if (goff[s] >= 0) v = fmaxf(fmaf(bufp[idx], sc, sh), 0.f);
            bufp[idx] = v;
        }
        __syncthreads();

        if (c0 + 1 < CIN) {
            issue_in(inB + (c0 + 1) * chanStride, cur ^ 1);
            issue_w(c0 + 1, cur ^ 1);
            cpCommit();
        }

        const float* wCur = &sW[cur * NW];
#pragma unroll
        for (int kd = 0; kd < 3; kd++)
#pragma unroll
            for (int kh = 0; kh < 3; kh++) {
                int k9 = kd * 3 + kh;
                // hoist weights for all 3 kw (shared by both x-halves)
                const float* wb_ = &wCur[(k9 * 3) * COUTB + group * OCPT];
                ulonglong2 wq[3][2];
#pragma unroll
                for (int kw = 0; kw < 3; kw++) {
#pragma unroll
                    for (int pp = 0; pp < 2; pp++)
                        wq[kw][pp] = *reinterpret_cast<const ulonglong2*>(
                            wb_ + kw * COUTB + pp * 4);
                }
                const float* rowp =
                    &bufp[((2 * oz + kd) * IYE + (2 * oy + kh)) * IXP + 16 * oxv];
#pragma unroll
                for (int h = 0; h < 2; h++) {
                    const float* ip = rowp + 8 * h;
                    float4 va = *reinterpret_cast<const float4*>(ip);
                    float4 vb = *reinterpret_cast<const float4*>(ip + 4);
                    float v8 = ip[8];
                    u64t ivd[9];
                    ivd[0] = pack2f(va.x, va.x); ivd[1] = pack2f(va.y, va.y);
                    ivd[2] = pack2f(va.z, va.z); ivd[3] = pack2f(va.w, va.w);
                    ivd[4] = pack2f(vb.x, vb.x); ivd[5] = pack2f(vb.y, vb.y);
                    ivd[6] = pack2f(vb.z, vb.z); ivd[7] = pack2f(vb.w, vb.w);
                    ivd[8] = pack2f(v8, v8);
#pragma unroll
                    for (int kw = 0; kw < 3; kw++) {
#pragma unroll
                        for (int u = 0; u < 4; u++) {
                            u64t iv = ivd[2 * u + kw];
                            ffma2(acc[0][h][u], wq[kw][0].x, iv);
                            ffma2(acc[1][h][u], wq[kw][0].y, iv);
                            ffma2(acc[2][h][u], wq[kw][1].x, iv);
                            ffma2(acc[3][h][u], wq[kw][1].y, iv);
                        }
                    }
                }
            }
    }

    int gz = tz * 4 + oz, gy = ty * 4 + oy;
    int gxBase = tx * 16 + oxv * 8;
#pragma unroll 1
    for (int p = 0; p < NPAIR; p++) {
        float o0[2][4], o1[2][4];
#pragma unroll
        for (int h = 0; h < 2; h++)
#pragma unroll
            for (int u = 0; u < 4; u++) unpack2f(acc[p][h][u], o0[h][u], o1[h][u]);
#pragma unroll
        for (int hh = 0; hh < 2; hh++) {
            int ocl = group * OCPT + 2 * p + hh;
            float bb = bias[ocl];
            float s = 0.f, q = 0.f;
#pragma unroll
            for (int h = 0; h < 2; h++) {
                float a0 = (hh ? o1[h][0] : o0[h][0]) + bb;
                float a1 = (hh ? o1[h][1] : o0[h][1]) + bb;
                float a2 = (hh ? o1[h][2] : o0[h][2]) + bb;
                float a3 = (hh ? o1[h][3] : o0[h][3]) + bb;
                *reinterpret_cast<float4*>(
                    &out[(((b * COUTB + ocl) * Dout + gz) * Dout + gy) * Dout +
                         gxBase + 4 * h]) = make_float4(a0, a1, a2, a3);
                s += a0 + a1 + a2 + a3;
                q += a0 * a0 + a1 * a1 + a2 * a2 + a3 * a3;
            }
#pragma unroll
            for (int off = 16; off > 0; off >>= 1) {
                s += __shfl_down_sync(0xffffffffu, s, off);
                q += __shfl_down_sync(0xffffffffu, q, off);
            }
            if (vt == 0) { bsum[ocl] = s; bsq[ocl] = q; }
        }
    }
    __syncthreads();
    if (tid < COUTB) {
        atomicAdd(&stats[tid], (double)bsum[tid]);
        atomicAdd(&stats[COUTB + tid], (double)bsq[tid]);
    }
}

// ---------------- conv_s2_v11b: cp.async double-buffered loader (stages 2/3) -------
template <int CIN, int COUTT, int COUTB, int OCPT, int MAXB>
__global__ void __launch_bounds__(128, MAXB) conv_s2_v11b(
    const float* __restrict__ in, const float* __restrict__ wT,
    const float* __restrict__ bias,
    const double* __restrict__ statsPrev, const float* __restrict__ gPrev,
    const float* __restrict__ bePrev, float invN,
    float* __restrict__ out, double* __restrict__ stats,
    int Din, int Dout, int ntx, int nty) {
    constexpr int GROUPS = COUTB / OCPT;
    constexpr int THREADS = 32 * GROUPS;
    constexpr int NPAIR = OCPT / 2;
    constexpr int IZ = 9, IYE = 9, IX = 17, IXP = 20;
    constexpr int NINF = IZ * IYE * IXP;
    constexpr int NSLOT = (NINF + THREADS - 1) / THREADS;
    constexpr int INB = NSLOT * THREADS;
    constexpr int NW = COUTB * 27;
    static_assert(THREADS == 128, "tile mapping assumes 128 threads");
    static_assert((NPAIR & 1) == 0, "NPAIR must be even");

    extern __shared__ float sm[];
    float* sIn = sm;
    float* sW  = sm + 2 * INB;
    __shared__ float bsum[COUTB], bsq[COUTB];
    __shared__ float sScale[CIN], sShift[CIN];

    int tid = threadIdx.x;
    int b = blockIdx.y;
    int ocBase = blockIdx.z * COUTB;
    int t = blockIdx.x;
    int tx = t % ntx, ty = (t / ntx) % nty, tz = t / (ntx * nty);

    int vt = tid & 31;
    int group = tid >> 5;
    int oxv = vt & 1;
    int oy  = (vt >> 1) & 3;
    int oz  = vt >> 3;

    bn_finalize_smem(statsPrev, gPrev, bePrev, invN, CIN, tid, sScale, sShift);

    int ginz = tz * 8 - 1;
    int giny = ty * 8 - 1;
    int ginx = tx * 16 - 1;

    const float* inB = in + (long long)b * CIN * Din * Din * Din;
    const int chanStride = Din * Din * Din;

    int goff[NSLOT];
    {
        int i = tid;
#pragma unroll
        for (int s = 0; s < NSLOT; s++, i += THREADS) {
            int ix = i % IXP;
            int r  = i / IXP;
            int iy = r % IYE;
            int iz = r / IYE;
            int gz = ginz + iz, gy = giny + iy, gx = ginx + ix;
            bool ok = (i < NINF) && (ix < IX) &&
                      ((unsigned)gz < (unsigned)Din) &&
                      ((unsigned)gy < (unsigned)Din) &&
                      ((unsigned)gx < (unsigned)Din);
            goff[s] = ok ? ((gz * Din + gy) * Din + gx) : -1;
        }
    }

    unsigned inAddr0 = toShared(&sIn[tid]);
    unsigned wAddr0  = toShared(sW);

    auto issue_in = [&](const float* inC, int buf) {
        unsigned base = inAddr0 + (unsigned)(buf * INB) * 4u;
#pragma unroll
        for (int s = 0; s < NSLOT; s++) {
            int pk = goff[s];
            if (pk >= 0) cpAsync4(base + (unsigned)(s * THREADS) * 4u, inC + pk);
        }
    };
    auto issue_w = [&](int c0, int buf) {
        const float* srcw = wT + c0 * 27 * COUTT;
        unsigned base = wAddr0 + (unsigned)(buf * NW) * 4u;
        if (COUTB == COUTT) {
#pragma unroll
            for (int i = tid * 4; i < NW; i += THREADS * 4)
                cpAsync16(base + (unsigned)i * 4u, &srcw[i]);
        } else {
#pragma unroll
            for (int i = tid * 4; i < NW; i += THREADS * 4) {
                int ocl = i % COUTB;
                int row = i / COUTB;
                cpAsync16(base + (unsigned)i * 4u, &srcw[row * COUTT + ocBase + ocl]);
            }
        }
    };

    u64t acc[NPAIR][4];
#pragma unroll
    for (int p = 0; p < NPAIR; p++)
#pragma unroll
        for (int u = 0; u < 4; u++) acc[p][u] = 0ULL;

    issue_in(inB, 0);
    issue_w(0, 0);
    cpCommit();

    __syncthreads();

#pragma unroll 1
    for (int c0 = 0; c0 < CIN; c0++) {
        int cur = c0 & 1;
        cpWait0();
        float sc = sScale[c0], sh = sShift[c0];
        float* bufp = &sIn[cur * INB];
#pragma unroll
        for (int s = 0; s < NSLOT; s++) {
            int idx = s * THREADS + tid;
            float v = 0.f;
            if (goff[s] >= 0) v = fmaxf(fmaf(bufp[idx], sc, sh), 0.f);
            bufp[idx] = v;
        }
        __syncthreads();

        if (c0 + 1 < CIN) {
            issue_in(inB + (c0 + 1) * chanStride, cur ^ 1);
            issue_w(c0 + 1, cur ^ 1);
            cpCommit();
        }

        const float* wCur = &sW[cur * NW];
#pragma unroll
        for (int kd = 0; kd < 3; kd++)
#pragma unroll
            for (int kh = 0; kh < 3; kh++) {
                const float* ip =
                    &bufp[((2 * oz + kd) * IYE + (2 * oy + kh)) * IXP + 8 * oxv];
                float4 va = *reinterpret_cast<const float4*>(ip);
                float4 vb = *reinterpret_cast<const float4*>(ip + 4);
                float v8 = ip[8];
                u64t ivd[9];
                ivd[0] = pack2f(va.x, va.x); ivd[1] = pack2f(va.y, va.y);
                ivd[2] = pack2f(va.z, va.z); ivd[3] = pack2f(va.w, va.w);
                ivd[4] = pack2f(vb.x, vb.x); ivd[5] = pack2f(vb.y, vb.y);
                ivd[6] = pack2f(vb.z, vb.z); ivd[7] = pack2f(vb.w, vb.w);
                ivd[8] = pack2f(v8, v8);
                int k9 = kd * 3 + kh;
                const float* wb_ = &wCur[(k9 * 3) * COUTB + group * OCPT];
#pragma unroll
                for (int kw = 0; kw < 3; kw++) {
                    ulonglong2 wq[NPAIR / 2];
#pragma unroll
                    for (int pp = 0; pp < NPAIR / 2; pp++)
                        wq[pp] = *reinterpret_cast<const ulonglong2*>(
                            wb_ + kw * COUTB + pp * 4);
#pragma unroll
                    for (int u = 0; u < 4; u++) {
                        u64t iv = ivd[2 * u + kw];
#pragma unroll
                        for (int pp = 0; pp < NPAIR / 2; pp++) {
                            ffma2(acc[2 * pp][u], wq[pp].x, iv);
                            ffma2(acc[2 * pp + 1][u], wq[pp].y, iv);
                        }
                    }
                }
            }
    }

    int gz = tz * 4 + oz, gy = ty * 4 + oy;
    int gx = tx * 8 + oxv * 4;
#pragma unroll 1
    for (int p = 0; p < NPAIR; p++) {
        float o0[4], o1[4];
#pragma unroll
        for (int u = 0; u < 4; u++) unpack2f(acc[p][u], o0[u], o1[u]);
#pragma unroll
        for (int h = 0; h < 2; h++) {
            float* ov = h ? o1 : o0;
            int ocl = group * OCPT + 2 * p + h;
            int oc = ocBase + ocl;
            float bb = bias[oc];
            float a0 = ov[0] + bb, a1 = ov[1] + bb, a2 = ov[2] + bb, a3 = ov[3] + bb;
            *reinterpret_cast<float4*>(
                &out[(((b * COUTT + oc) * Dout + gz) * Dout + gy) * Dout + gx]) =
                make_float4(a0, a1, a2, a3);

            float s = a0 + a1 + a2 + a3;
            float q = a0 * a0 + a1 * a1 + a2 * a2 + a3 * a3;
#pragma unroll
            for (int off = 16; off > 0; off >>= 1) {
                s += __shfl_down_sync(0xffffffffu, s, off);
                q += __shfl_down_sync(0xffffffffu, q, off);
            }
            if (vt == 0) { bsum[ocl] = s; bsq[ocl] = q; }
        }
    }
    __syncthreads();
    if (tid < COUTB) {
        atomicAdd(&stats[ocBase + tid], (double)bsum[tid]);
        atomicAdd(&stats[COUTT + ocBase + tid], (double)bsq[tid]);
    }
}

// ---------------- old generic stride-2 conv (stage 4) + inline finalize ------------
template <int CIN, int COUTB, int OCPT>
__global__ void __launch_bounds__(128) conv_s2_kernel(
    const float* __restrict__ in, const float* __restrict__ w,
    const float* __restrict__ bias,
    const double* __restrict__ statsPrev, const float* __restrict__ gPrev,
    const float* __restrict__ bePrev, float invN,
    float* __restrict__ out, double* __restrict__ stats,
    int Din, int Dout, int ntile, int coutTot) {
    constexpr int ICC = 16;
    constexpr int NIN = ICC * 729;
    constexpr int NW  = COUTB * ICC * 27;
    extern __shared__ float sm[];
    float* sIn = sm;
    float* sW  = sm + NIN;
    __shared__ float bsum[COUTB], bsq[COUTB];
    __shared__ float sScale[CIN], sShift[CIN];

    int tid = threadIdx.x;
    int b = blockIdx.y;
    int ocBase = blockIdx.z * COUTB;
    int t = blockIdx.x;
    int tz = t / (ntile * ntile), ty = (t / ntile) % ntile, tx = t % ntile;
    int pair = tid & 31, group = tid >> 5;
    int oz = pair >> 3, oy = (pair >> 1) & 3, px = pair & 1;

    bn_finalize_smem(statsPrev, gPrev, bePrev, invN, CIN, tid, sScale, sShift);

    if (tid < COUTB) { bsum[tid] = 0.f; bsq[tid] = 0.f; }

    float acc0[OCPT], acc1[OCPT];
#pragma unroll
    for (int j = 0; j < OCPT; j++) { acc0[j] = 0.f; acc1[j] = 0.f; }

    for (int c0 = 0; c0 < CIN; c0 += ICC) {
        __syncthreads();
        for (int i = tid; i < NIN; i += 128) {
            int ic = i / 729, r = i % 729;
            int iz = r / 81, iy = (r / 9) % 9, ix = r % 9;
            int gz = tz * 8 - 1 + iz, gy = ty * 8 - 1 + iy, gx = tx * 8 - 1 + ix;
            float v = 0.f;
            if ((unsigned)gz < (unsigned)Din && (unsigned)gy < (unsigned)Din &&
                (unsigned)gx < (unsigned)Din) {
                v = in[(((b * CIN + c0 + ic) * Din + gz) * Din + gy) * Din + gx];
                v = fmaxf(fmaf(v, sScale[c0 + ic], sShift[c0 + ic]), 0.f);
            }
            sIn[i] = v;
        }
        for (int i = tid; i < NW; i += 128) {
            int ocl = i / (ICC * 27), r = i % (ICC * 27);
            sW[i] = w[((ocBase + ocl) * CIN + c0) * 27 + r];
        }
        __syncthreads();

#pragma unroll 1
        for (int ic = 0; ic < ICC; ic++) {
            const float* wrow = &sW[(group * OCPT) * ICC * 27 + ic * 27];
#pragma unroll
            for (int kd = 0; kd < 3; kd++)
#pragma unroll
                for (int kh = 0; kh < 3; kh++) {
                    int base = ((ic * 9 + (2 * oz + kd)) * 9 + (2 * oy + kh)) * 9 + 4 * px;
                    float ivs[5];
#pragma unroll
                    for (int u = 0; u < 5; u++) ivs[u] = sIn[base + u];
#pragma unroll
                    for (int kw = 0; kw < 3; kw++) {
#pragma unroll
                        for (int j = 0; j < OCPT; j++) {
                            float wv = wrow[j * ICC * 27 + (kd * 3 + kh) * 3 + kw];
                            acc0[j] = fmaf(ivs[kw], wv, acc0[j]);
                            acc1[j] = fmaf(ivs[kw + 2], wv, acc1[j]);
                        }
                    }
                }
        }
    }

    int gz = tz * 4 + oz, gy = ty * 4 + oy, gx = tx * 4 + 2 * px;
#pragma unroll
    for (int j = 0; j < OCPT; j++) {
        int oc = ocBase + group * OCPT + j;
        float bb = bias[oc];
        float o0 = acc0[j] + bb, o1 = acc1[j] + bb;
        *reinterpret_cast<float2*>(
            &out[(((b * coutTot + oc) * Dout + gz) * Dout + gy) * Dout + gx]) =
            make_float2(o0, o1);

        float s = o0 + o1, q = o0 * o0 + o1 * o1;
#pragma unroll
        for (int off = 16; off > 0; off >>= 1) {
            s += __shfl_down_sync(0xffffffffu, s, off);
            q += __shfl_down_sync(0xffffffffu, q, off);
        }
        if (pair == 0) {
            atomicAdd(&bsum[group * OCPT + j], s);
            atomicAdd(&bsq[group * OCPT + j], q);
        }
    }
    __syncthreads();
    if (tid < COUTB) {
        atomicAdd(&stats[ocBase + tid], (double)bsum[tid]);
        atomicAdd(&stats[coutTot + ocBase + tid], (double)bsq[tid]);
    }
}

// ---------------- heads: BN finalize + 12 dot products + matrix composition --------
__device__ __forceinline__ void ident4(float* M) {
#pragma unroll
    for (int i = 0; i < 16; i++) M[i] = (i % 5 == 0) ? 1.f : 0.f;
}
__device__ __forceinline__ void mm4(const float* A, const float* B, float* C) {
#pragma unroll
    for (int i = 0; i < 4; i++)
#pragma unroll
        for (int j = 0; j < 4; j++)
            C[i * 4 + j] = A[i * 4 + 0] * B[0 + j] + A[i * 4 + 1] * B[4 + j] +
                           A[i * 4 + 2] * B[8 + j] + A[i * 4 + 3] * B[12 + j];
}

__global__ void __launch_bounds__(256) heads_kernel(
    const float* __restrict__ xs,
    const double* __restrict__ statsPrev, const float* __restrict__ gPrev,
    const float* __restrict__ bePrev, float invN,
    const float* __restrict__ tw, const float* __restrict__ tb,
    const float* __restrict__ rw, const float* __restrict__ rb,
    const float* __restrict__ sw_, const float* __restrict__ sb_,
    const float* __restrict__ shw, const float* __restrict__ shb,
    float* __restrict__ theta) {
    __shared__ float red[12 * 256];
    __shared__ float ssc[64], ssh[64];
    int b = blockIdx.x, tid = threadIdx.x;
    bn_finalize_smem(statsPrev, gPrev, bePrev, invN, 64, tid, ssc, ssh);
    __syncthreads();
    float p[12];
#pragma unroll
    for (int r = 0; r < 12; r++) p[r] = 0.f;
    for (int i = tid; i < 4096; i += 256) {
        int c = i >> 6;
        float v = fmaxf(fmaf(xs[b * 4096 + i], ssc[c], ssh[c]), 0.f);
#pragma unroll
        for (int r = 0; r < 3; r++) {
            p[r]     = fmaf(v, tw[r * 4096 + i], p[r]);
            p[3 + r] = fmaf(v, rw[r * 4096 + i], p[3 + r]);
            p[6 + r] = fmaf(v, sw_[r * 4096 + i], p[6 + r]);
            p[9 + r] = fmaf(v, shw[r * 4096 + i], p[9 + r]);
        }
    }
#pragma unroll
    for (int r = 0; r < 12; r++) red[r * 256 + tid] = p[r];
    __syncthreads();
    for (int s = 128; s > 0; s >>= 1) {
        if (tid < s)
#pragma unroll
            for (int r = 0; r < 12; r++) red[r * 256 + tid] += red[r * 256 + tid + s];
        __syncthreads();
    }
    if (tid == 0) {
        const float PI4 = 0.7853981633974483f;
        float tr[3], ro[3], scp[3], shp[3];
#pragma unroll
        for (int r = 0; r < 3; r++) {
            tr[r]  = tanhf(red[r * 256] + tb[r]) * 0.1f;
            ro[r]  = tanhf(red[(3 + r) * 256] + rb[r]) * PI4;
            scp[r] = tanhf(red[(6 + r) * 256] + sb_[r]) * 0.2f;
            shp[r] = tanhf(red[(9 + r) * 256] + shb[r]) * PI4;
        }
        float c0 = cosf(ro[0]), s0 = sinf(ro[0]);
        float c1 = cosf(ro[1]), s1 = sinf(ro[1]);
        float c2 = cosf(ro[2]), s2 = sinf(ro[2]);
        float cs0 = cosf(shp[0]), ss0 = sinf(shp[0]);
        float cs1 = cosf(shp[1]), ss1 = sinf(shp[1]);
        float cs2 = cosf(shp[2]), ss2 = sinf(shp[2]);

        float T[16], R1[16], R2[16], R3[16], S[16], H1[16], H2[16], H3[16];
        float R[16], Sh[16], ShT[16], A[16], B[16];
        ident4(T);  T[3] = tr[0]; T[7] = tr[1]; T[11] = tr[2];
        ident4(R1); R1[0] = c0; R1[1] = -s0; R1[4] = s0; R1[5] = c0;
        ident4(R2); R2[5] = c1; R2[6] = -s1; R2[9] = s1; R2[10] = c1;
        ident4(R3); R3[0] = c2; R3[1] = -s2; R3[4] = s2; R3[5] = c2;
        ident4(S);  S[0] = expf(scp[0]); S[5] = expf(scp[1]); S[10] = expf(scp[2]);
        ident4(H1); H1[5] = cs0; H1[6] = -ss0; H1[9] = ss0; H1[10] = cs0;
        ident4(H2); H2[0] = cs1; H2[2] = ss1; H2[8] = -ss1; H2[10] = cs1;
        ident4(H3); H3[0] = cs2; H3[1] = -ss2; H3[4] = ss2; H3[5] = cs2;

        mm4(R1, R2, A); mm4(A, R3, R);
        mm4(H1, H2, A); mm4(A, H3, Sh);
#pragma unroll
        for (int i = 0; i < 4; i++)
#pragma unroll
            for (int j = 0; j < 4; j++) ShT[i * 4 + j] = Sh[j * 4 + i];
        mm4(Sh, S, A); mm4(A, ShT, B); mm4(B, R, A); mm4(A, T, B);
#pragma unroll
        for (int i = 0; i < 12; i++) theta[b * 12 + i] = B[i];
    }
}

// ---------------- trilinear grid sample (zero padding, clamped gather) ----------------
__global__ void __launch_bounds__(256) sampler_kernel(
    const float* __restrict__ x, const float* __restrict__ theta,
    float* __restrict__ out) {
    int idx = blockIdx.x * 256 + threadIdx.x;
    int b = idx >> 18;
    int r = idx & 262143;
    int z = r >> 12, y = (r >> 6) & 63, xq = r & 63;
    const float st = 2.f / 63.f;
    float xx = fmaf((float)xq, st, -1.f);
    float yy = fmaf((float)y, st, -1.f);
    float zz = fmaf((float)z, st, -1.f);
    const float* th = &theta[b * 12];
    float g0 = th[0] * xx + th[1] * yy + th[2] * zz + th[3];
    float g1 = th[4] * xx + th[5] * yy + th[6] * zz + th[7];
    float g2 = th[8] * xx + th[9] * yy + th[10] * zz + th[11];
    float fx = ((g0 + 1.f) * 64.f - 1.f) * 0.5f;
    float fy = ((g1 + 1.f) * 64.f - 1.f) * 0.5f;
    float fz = ((g2 + 1.f) * 64.f - 1.f) * 0.5f;
    float x0f = floorf(fx), y0f = floorf(fy), z0f = floorf(fz);
    int x0 = (int)x0f, y0 = (int)y0f, z0 = (int)z0f;
    float wx1 = fx - x0f, wx0 = 1.f - wx1;
    float wy1 = fy - y0f, wy0 = 1.f - wy1;
    float wz1 = fz - z0f, wz0 = 1.f - wz1;
    const float* xb = &x[b << 18];
    float acc = 0.f;
#pragma unroll
    for (int dz = 0; dz < 2; dz++) {
        int zc = z0 + dz;
        float wz = dz ? wz1 : wz0;
        bool vz = (zc >= 0 && zc < 64);
        int zi = min(max(zc, 0), 63);
#pragma unroll
        for (int dy = 0; dy < 2; dy++) {
            int yc = y0 + dy;
            float wy = dy ? wy1 : wy0;
            bool vy = vz && (yc >= 0 && yc < 64);
            int yi = min(max(yc, 0), 63);
#pragma unroll
            for (int dx = 0; dx < 2; dx++) {
                int xc = x0 + dx;
                float wgt = wz * wy * (dx ? wx1 : wx0);
                bool v = vy && (xc >= 0 && xc < 64);
                int xi = min(max(xc, 0), 63);
                float val = xb[(zi * 64 + yi) * 64 + xi];
                acc += v ? val * wgt : 0.f;
            }
        }
    }
    out[idx] = acc;
}

// ---------------- launch ----------------
extern "C" void kernel_launch(void* const* d_in, const int* in_sizes, int n_in,
                              void* d_out, int out_size) {
    const float* x    = (const float*)d_in[0];
    const float* w00  = (const float*)d_in[1];
    const float* b00  = (const float*)d_in[2];
    const float* g00  = (const float*)d_in[3];
    const float* be00 = (const float*)d_in[4];
    const float* w0   = (const float*)d_in[5];
    const float* b0   = (const float*)d_in[6];
    const float* g0   = (const float*)d_in[7];
    const float* be0  = (const float*)d_in[8];
    const float* w1   = (const float*)d_in[9];
    const float* b1   = (const float*)d_in[10];
    const float* g1   = (const float*)d_in[11];
    const float* be1  = (const float*)d_in[12];
    const float* w2   = (const float*)d_in[13];
    const float* b2   = (const float*)d_in[14];
    const float* g2   = (const float*)d_in[15];
    const float* be2  = (const float*)d_in[16];
    const float* w3   = (const float*)d_in[17];
    const float* b3   = (const float*)d_in[18];
    const float* g3   = (const float*)d_in[19];
    const float* be3  = (const float*)d_in[20];
    const float* tw   = (const float*)d_in[21];
    const float* tb   = (const float*)d_in[22];
    const float* rw   = (const float*)d_in[23];
    const float* rb   = (const float*)d_in[24];
    const float* sw   = (const float*)d_in[25];
    const float* sb   = (const float*)d_in[26];
    const float* shw  = (const float*)d_in[27];
    const float* shb  = (const float*)d_in[28];

    float *buf0, *buf1, *buf2, *buf3, *buf4, *theta;
    float *wT0, *wT1, *wT2;
    double* stats;
    cudaGetSymbolAddress((void**)&buf0, g_buf0);
    cudaGetSymbolAddress((void**)&buf1, g_buf1);
    cudaGetSymbolAddress((void**)&buf2, g_buf2);
    cudaGetSymbolAddress((void**)&buf3, g_buf3);
    cudaGetSymbolAddress((void**)&buf4, g_buf4);
    cudaGetSymbolAddress((void**)&stats, g_stats);
    cudaGetSymbolAddress((void**)&theta, g_theta);
    cudaGetSymbolAddress((void**)&wT0, g_wT0);
    cudaGetSymbolAddress((void**)&wT1, g_wT1);
    cudaGetSymbolAddress((void**)&wT2, g_wT2);

    // smem
    const int SM_S1 = 2 * 23 * 128 * 4 + 2 * 32 * 27 * 4;  // v12: 30464
    const int SM_S2 = 2 * 13 * 128 * 4 + 2 * 64 * 27 * 4;  // 27136
    const int SM_S3 = 2 * 13 * 128 * 4 + 2 * 32 * 27 * 4;  // 20224
    const int SM_L4 = (16 * 729 + 16 * 16 * 27) * 4;       // 74304 (stage 4)
    cudaFuncSetAttribute(conv_s2_v12<16, 4>,
                         cudaFuncAttributeMaxDynamicSharedMemorySize, SM_S1);
    cudaFuncSetAttribute(conv_s2_kernel<64, 16, 4>,
                         cudaFuncAttributeMaxDynamicSharedMemorySize, SM_L4);

    // 1: prep (zero stats + all weight transposes)
    prep_kernel<<<702, 256>>>(w0, w1, w2, wT0, wT1, wT2, stats);

    // 2: conv00 1->16, 64^3
    conv00_v2<<<dim3(512, 16), 128>>>(x, w00, b00, buf0, stats + 0);

    // 3: stage 1: 16->32, 64^3 -> 32^3; v12 tile 4x4x16: ntx=2,nty=8,ntz=8 -> 128
    conv_s2_v12<16, 4><<<dim3(128, 16, 1), 128, SM_S1>>>(
        buf0, wT0, b0, stats + 0, g00, be00, 1.f / 4194304.f,
        buf1, stats + 32, 64, 32, 2, 8);

    // 4: stage 2: 32->64, 32^3 -> 16^3; 32 tiles, full 64 oc, OCPT=16 -> 512 blocks
    conv_s2_v11b<32, 64, 64, 16, 4><<<dim3(32, 16, 1), 128, SM_S2>>>(
        buf1, wT1, b1, stats + 32, g0, be0, 1.f / 524288.f,
        buf2, stats + 96, 32, 16, 2, 4);

    // 5: stage 3: 64->64, 16^3 -> 8^3; 4 tiles x oc-split z=2 -> 128 blocks
    conv_s2_v11b<64, 64, 32, 8, 5><<<dim3(4, 16, 2), 128, SM_S3>>>(
        buf2, wT2, b2, stats + 96, g1, be1, 1.f / 65536.f,
        buf3, stats + 224, 16, 8, 1, 2);

    // 6: stage 4: 64->64, 8^3 -> 4^3 (tiny; old kernel, oc split z=4)
    conv_s2_kernel<64, 16, 4><<<dim3(1, 16, 4), 128, SM_L4>>>(
        buf3, w3, b3, stats + 224, g2, be2, 1.f / 8192.f,
        buf4, stats + 352, 8, 4, 1, 64);

    // 7: heads (inlines stage-4 BN finalize)
    heads_kernel<<<16, 256>>>(buf4, stats + 352, g3, be3, 1.f / 1024.f,
                              tw, tb, rw, rb, sw, sb, shw, shb, theta);

    // 8: grid sample
    sampler_kernel<<<16384, 256>>>(x, theta, (float*)d_out);
}